// round 13
// baseline (speedup 1.0000x reference)
#include <cuda_runtime.h>
#include <cuda_bf16.h>
#include <cstdint>

// Problem constants
#define Bn 8
#define Nn 1024
#define Dn 1024
#define Hn 16
#define DHn 64
#define D3 3072
#define Kdim 1024

// ---------------------------------------------------------------------------
// Device scratch (allocation-free)
// ---------------------------------------------------------------------------
__device__ __nv_bfloat16 g_xhi[(size_t)Bn * Nn * Dn];
__device__ __nv_bfloat16 g_xlo[(size_t)Bn * Nn * Dn];
__device__ __nv_bfloat16 g_wqkvThi[(size_t)D3 * Dn];
__device__ __nv_bfloat16 g_wqkvTlo[(size_t)D3 * Dn];
__device__ __nv_bfloat16 g_woutThi[(size_t)Dn * Dn];
__device__ __nv_bfloat16 g_woutTlo[(size_t)Dn * Dn];
__device__ __nv_bfloat16 g_hhi[(size_t)Bn * Nn * Dn];
__device__ __nv_bfloat16 g_hlo[(size_t)Bn * Nn * Dn];
#define HEADELEMS ((size_t)Bn * Hn * Nn * DHn)
__device__ __nv_bfloat16 g_qhi[HEADELEMS];
__device__ __nv_bfloat16 g_qlo[HEADELEMS];
__device__ __nv_bfloat16 g_khi[HEADELEMS];
__device__ __nv_bfloat16 g_klo[HEADELEMS];
__device__ __nv_bfloat16 g_vhi[HEADELEMS];
__device__ __nv_bfloat16 g_vlo[HEADELEMS];
__device__ float g_rowinv[(size_t)Bn * Hn * Nn];   // 1/rowsum per (b,h,q)

// ---------------------------------------------------------------------------
// PTX helpers (baseline sm_80+ features only)
// ---------------------------------------------------------------------------
__device__ __forceinline__ uint32_t smem_u32(const void* p) {
    uint32_t a;
    asm("{ .reg .u64 t; cvta.to.shared.u64 t, %1; cvt.u32.u64 %0, t; }"
        : "=r"(a) : "l"(p));
    return a;
}

#define CP_ASYNC16(dst, gsrc) \
    asm volatile("cp.async.cg.shared.global [%0], [%1], 16;" :: "r"(dst), "l"(gsrc))
#define CP_COMMIT() asm volatile("cp.async.commit_group;" ::: "memory")
#define CP_WAIT2()  asm volatile("cp.async.wait_group 2;" ::: "memory")
#define CP_WAIT1()  asm volatile("cp.async.wait_group 1;" ::: "memory")
#define CP_WAIT0()  asm volatile("cp.async.wait_group 0;" ::: "memory")

#define LDSM_X4(r0, r1, r2, r3, addr) \
    asm volatile("ldmatrix.sync.aligned.m8n8.x4.shared.b16 {%0,%1,%2,%3}, [%4];" \
                 : "=r"(r0), "=r"(r1), "=r"(r2), "=r"(r3) : "r"(addr))

#define LDSM_X4_T(r0, r1, r2, r3, addr) \
    asm volatile("ldmatrix.sync.aligned.m8n8.x4.trans.shared.b16 {%0,%1,%2,%3}, [%4];" \
                 : "=r"(r0), "=r"(r1), "=r"(r2), "=r"(r3) : "r"(addr))

#define MMA16816(d, a, b) \
    asm volatile("mma.sync.aligned.m16n8k16.row.col.f32.bf16.bf16.f32 " \
                 "{%0,%1,%2,%3}, {%4,%5,%6,%7}, {%8,%9}, {%0,%1,%2,%3};" \
                 : "+f"((d)[0]), "+f"((d)[1]), "+f"((d)[2]), "+f"((d)[3]) \
                 : "r"((a)[0]), "r"((a)[1]), "r"((a)[2]), "r"((a)[3]), \
                   "r"((b)[0]), "r"((b)[1]))

__device__ __forceinline__ uint32_t pack_split(float2 p, uint32_t& lo) {
    __nv_bfloat16 hx = __float2bfloat16(p.x), hy = __float2bfloat16(p.y);
    __nv_bfloat16 lx = __float2bfloat16(p.x - __bfloat162float(hx));
    __nv_bfloat16 ly = __float2bfloat16(p.y - __bfloat162float(hy));
    __nv_bfloat162 hv = __halves2bfloat162(hx, hy);
    __nv_bfloat162 lv = __halves2bfloat162(lx, ly);
    lo = *(uint32_t*)&lv;
    return *(uint32_t*)&hv;
}

// swizzled address in a 64B-row tile (gemm): chunk c ^ ((row>>1)&3)
#define SWADDR(base, row, c) \
    ((base) + (uint32_t)(row) * 64u + ((uint32_t)((c) ^ (((row) >> 1) & 3)) << 4))

// ---------------------------------------------------------------------------
// Split kernels
// ---------------------------------------------------------------------------
__global__ __launch_bounds__(256) void split_kernel(
    const float4* __restrict__ in, __nv_bfloat162* __restrict__ hi,
    __nv_bfloat162* __restrict__ lo, int n4)
{
    int i = blockIdx.x * 256 + threadIdx.x;
    if (i >= n4) return;
    float4 v = in[i];
    __nv_bfloat16 h0 = __float2bfloat16(v.x), h1 = __float2bfloat16(v.y);
    __nv_bfloat16 h2 = __float2bfloat16(v.z), h3 = __float2bfloat16(v.w);
    __nv_bfloat16 l0 = __float2bfloat16(v.x - __bfloat162float(h0));
    __nv_bfloat16 l1 = __float2bfloat16(v.y - __bfloat162float(h1));
    __nv_bfloat16 l2 = __float2bfloat16(v.z - __bfloat162float(h2));
    __nv_bfloat16 l3 = __float2bfloat16(v.w - __bfloat162float(h3));
    hi[2 * i]     = __halves2bfloat162(h0, h1);
    hi[2 * i + 1] = __halves2bfloat162(h2, h3);
    lo[2 * i]     = __halves2bfloat162(l0, l1);
    lo[2 * i + 1] = __halves2bfloat162(l2, l3);
}

__global__ __launch_bounds__(256) void splitT_kernel(
    const float* __restrict__ in, __nv_bfloat16* __restrict__ hiT,
    __nv_bfloat16* __restrict__ loT, int R, int C)
{
    __shared__ float t[32][33];
    int bx = blockIdx.x * 32;
    int by = blockIdx.y * 32;
    int x = threadIdx.x, y = threadIdx.y;  // 32 x 8
    #pragma unroll
    for (int i = y; i < 32; i += 8)
        t[i][x] = in[(size_t)(by + i) * C + bx + x];
    __syncthreads();
    #pragma unroll
    for (int i = y; i < 32; i += 8) {
        float v = t[x][i];
        __nv_bfloat16 h = __float2bfloat16(v);
        size_t o = (size_t)(bx + i) * R + by + x;
        hiT[o] = h;
        loT[o] = __float2bfloat16(v - __bfloat162float(h));
    }
}

// ---------------------------------------------------------------------------
// bf16-split GEMM, mode 1 (QKV projection + per-head split) — unchanged.
// ---------------------------------------------------------------------------
#define TILEB (128 * 64)
#define STAGEB (4 * TILEB)
#define NSTAGE 3
#define SMEM_GEMM (NSTAGE * STAGEB)    // 98304
#define NCHUNK (Kdim / 32)

__global__ __launch_bounds__(256, 2) void gemm_qkv(
    const __nv_bfloat16* __restrict__ Ahi, const __nv_bfloat16* __restrict__ Alo,
    const __nv_bfloat16* __restrict__ BThi, const __nv_bfloat16* __restrict__ BTlo,
    __nv_bfloat16* __restrict__ qhi, __nv_bfloat16* __restrict__ qlo,
    __nv_bfloat16* __restrict__ khi, __nv_bfloat16* __restrict__ klo,
    __nv_bfloat16* __restrict__ vhi, __nv_bfloat16* __restrict__ vlo)
{
    extern __shared__ char smem[];
    const uint32_t sb = smem_u32(smem);
    const int tid = threadIdx.x, wid = tid >> 5, lane = tid & 31;
    const int wm = wid >> 1;
    const int wn = wid & 1;
    const int ctaM = blockIdx.y * 128, ctaN = blockIdx.x * 128;

    const __nv_bfloat16* gsrc[4] = {
        Ahi + (size_t)ctaM * Kdim, Alo + (size_t)ctaM * Kdim,
        BThi + (size_t)ctaN * Kdim, BTlo + (size_t)ctaN * Kdim};

    auto load_chunk = [&](int s, int k0) {
        uint32_t base = sb + s * STAGEB;
        #pragma unroll
        for (int t = 0; t < 4; t++) {
            uint32_t tb = base + t * TILEB;
            const __nv_bfloat16* g = gsrc[t] + k0;
            #pragma unroll
            for (int i = tid; i < 512; i += 256) {
                int r = i >> 2, c = i & 3;
                uint32_t dst = SWADDR(tb, r, c);
                size_t gs = __cvta_generic_to_global(g + (size_t)r * Kdim + c * 8);
                CP_ASYNC16(dst, gs);
            }
        }
        CP_COMMIT();
    };

    float acc[2][8][4];
    #pragma unroll
    for (int i = 0; i < 2; i++)
        #pragma unroll
        for (int j = 0; j < 8; j++)
            #pragma unroll
            for (int k = 0; k < 4; k++) acc[i][j][k] = 0.f;

    load_chunk(0, 0);
    load_chunk(1, 32);

    const int q = lane >> 3, l8 = lane & 7;
    const int arow = wm * 32 + (q & 1) * 8 + l8;
    const int brow = wn * 64 + (q >> 1) * 8 + l8;
    const int acsel = q >> 1;
    const int bcsel = q & 1;

    for (int c = 0; c < NCHUNK; c++) {
        int s = c % NSTAGE;
        if (c == NCHUNK - 1) CP_WAIT0(); else CP_WAIT1();
        __syncthreads();

        uint32_t base = sb + s * STAGEB;
        uint32_t tAh = base, tAl = base + TILEB;
        uint32_t tBh = base + 2 * TILEB, tBl = base + 3 * TILEB;

        #pragma unroll
        for (int kk = 0; kk < 2; kk++) {
            int ca = kk * 2 + acsel;
            int cb = kk * 2 + bcsel;
            uint32_t ah[2][4], al[2][4];
            #pragma unroll
            for (int mf = 0; mf < 2; mf++) {
                int row = arow + mf * 16;
                LDSM_X4(ah[mf][0], ah[mf][1], ah[mf][2], ah[mf][3], SWADDR(tAh, row, ca));
                LDSM_X4(al[mf][0], al[mf][1], al[mf][2], al[mf][3], SWADDR(tAl, row, ca));
            }
            #pragma unroll
            for (int nf2 = 0; nf2 < 4; nf2++) {
                uint32_t bh0[2], bh1[2], bl0[2], bl1[2];
                int row = brow + nf2 * 16;
                LDSM_X4(bh0[0], bh0[1], bh1[0], bh1[1], SWADDR(tBh, row, cb));
                LDSM_X4(bl0[0], bl0[1], bl1[0], bl1[1], SWADDR(tBl, row, cb));
                int n0 = 2 * nf2, n1 = 2 * nf2 + 1;
                MMA16816(acc[0][n0], ah[0], bh0);
                MMA16816(acc[0][n1], ah[0], bh1);
                MMA16816(acc[1][n0], ah[1], bh0);
                MMA16816(acc[1][n1], ah[1], bh1);
                MMA16816(acc[0][n0], ah[0], bl0);
                MMA16816(acc[0][n1], ah[0], bl1);
                MMA16816(acc[1][n0], ah[1], bl0);
                MMA16816(acc[1][n1], ah[1], bl1);
                MMA16816(acc[0][n0], al[0], bh0);
                MMA16816(acc[0][n1], al[0], bh1);
                MMA16816(acc[1][n0], al[1], bh0);
                MMA16816(acc[1][n1], al[1], bh1);
            }
        }
        if (c + NSTAGE - 1 < NCHUNK) load_chunk((c + 2) % NSTAGE, (c + 2) * 32);
    }

    #pragma unroll
    for (int mf = 0; mf < 2; mf++) {
        int row = ctaM + wm * 32 + mf * 16 + (lane >> 2);
        int b = row >> 10, n = row & 1023;
        #pragma unroll
        for (int nf = 0; nf < 8; nf++) {
            int col = ctaN + wn * 64 + nf * 8 + (lane & 3) * 2;
            int s = col >> 10, hh = (col >> 6) & 15, dh = col & 63;
            float sc = (s == 0) ? 0.125f : 1.0f;
            __nv_bfloat16* hiP = (s == 0) ? qhi : (s == 1) ? khi : vhi;
            __nv_bfloat16* loP = (s == 0) ? qlo : (s == 1) ? klo : vlo;
            size_t o0 = (((size_t)(b * 16 + hh)) * 1024 + n) * 64 + dh;
            size_t o1 = o0 + 8 * 64;
            uint32_t lo;
            uint32_t hi = pack_split(
                make_float2(acc[mf][nf][0] * sc, acc[mf][nf][1] * sc), lo);
            *(uint32_t*)&hiP[o0] = hi;
            *(uint32_t*)&loP[o0] = lo;
            hi = pack_split(
                make_float2(acc[mf][nf][2] * sc, acc[mf][nf][3] * sc), lo);
            *(uint32_t*)&hiP[o1] = hi;
            *(uint32_t*)&loP[o1] = lo;
        }
    }
}

// ---------------------------------------------------------------------------
// bf16-split GEMM, mode 0 (output projection + bias) with attn normalize
// INTERLEAVED into the mainloop: per K-chunk, stream 8 attn rows (coalesced,
// uniform rowinv) so HBM latency hides under tensor work of the same block.
// Each block owns 256 contiguous attn rows (1 MB).
// ---------------------------------------------------------------------------
__global__ __launch_bounds__(256, 2) void gemm_out(
    const __nv_bfloat16* __restrict__ Ahi, const __nv_bfloat16* __restrict__ Alo,
    const __nv_bfloat16* __restrict__ BThi, const __nv_bfloat16* __restrict__ BTlo,
    float* __restrict__ C, const float* __restrict__ bias,
    float4* __restrict__ attn4, const float* __restrict__ rowinv)
{
    extern __shared__ char smem[];
    const uint32_t sb = smem_u32(smem);
    const int tid = threadIdx.x, wid = tid >> 5, lane = tid & 31;
    const int wm = wid >> 1;
    const int wn = wid & 1;
    const int ctaM = blockIdx.y * 128, ctaN = blockIdx.x * 128;
    const int bid = blockIdx.y * gridDim.x + blockIdx.x;
    const int row0 = bid * 256;               // this block's attn row range

    const __nv_bfloat16* gsrc[4] = {
        Ahi + (size_t)ctaM * Kdim, Alo + (size_t)ctaM * Kdim,
        BThi + (size_t)ctaN * Kdim, BTlo + (size_t)ctaN * Kdim};

    auto load_chunk = [&](int s, int k0) {
        uint32_t base = sb + s * STAGEB;
        #pragma unroll
        for (int t = 0; t < 4; t++) {
            uint32_t tb = base + t * TILEB;
            const __nv_bfloat16* g = gsrc[t] + k0;
            #pragma unroll
            for (int i = tid; i < 512; i += 256) {
                int r = i >> 2, c = i & 3;
                uint32_t dst = SWADDR(tb, r, c);
                size_t gs = __cvta_generic_to_global(g + (size_t)r * Kdim + c * 8);
                CP_ASYNC16(dst, gs);
            }
        }
        CP_COMMIT();
    };

    float acc[2][8][4];
    #pragma unroll
    for (int i = 0; i < 2; i++)
        #pragma unroll
        for (int j = 0; j < 8; j++)
            #pragma unroll
            for (int k = 0; k < 4; k++) acc[i][j][k] = 0.f;

    load_chunk(0, 0);
    load_chunk(1, 32);

    const int q = lane >> 3, l8 = lane & 7;
    const int arow = wm * 32 + (q & 1) * 8 + l8;
    const int brow = wn * 64 + (q >> 1) * 8 + l8;
    const int acsel = q >> 1;
    const int bcsel = q & 1;

    for (int c = 0; c < NCHUNK; c++) {
        int s = c % NSTAGE;
        if (c == NCHUNK - 1) CP_WAIT0(); else CP_WAIT1();
        __syncthreads();

        uint32_t base = sb + s * STAGEB;
        uint32_t tAh = base, tAl = base + TILEB;
        uint32_t tBh = base + 2 * TILEB, tBl = base + 3 * TILEB;

        #pragma unroll
        for (int kk = 0; kk < 2; kk++) {
            int ca = kk * 2 + acsel;
            int cb = kk * 2 + bcsel;
            uint32_t ah[2][4], al[2][4];
            #pragma unroll
            for (int mf = 0; mf < 2; mf++) {
                int row = arow + mf * 16;
                LDSM_X4(ah[mf][0], ah[mf][1], ah[mf][2], ah[mf][3], SWADDR(tAh, row, ca));
                LDSM_X4(al[mf][0], al[mf][1], al[mf][2], al[mf][3], SWADDR(tAl, row, ca));
            }
            #pragma unroll
            for (int nf2 = 0; nf2 < 4; nf2++) {
                uint32_t bh0[2], bh1[2], bl0[2], bl1[2];
                int row = brow + nf2 * 16;
                LDSM_X4(bh0[0], bh0[1], bh1[0], bh1[1], SWADDR(tBh, row, cb));
                LDSM_X4(bl0[0], bl0[1], bl1[0], bl1[1], SWADDR(tBl, row, cb));
                int n0 = 2 * nf2, n1 = 2 * nf2 + 1;
                MMA16816(acc[0][n0], ah[0], bh0);
                MMA16816(acc[0][n1], ah[0], bh1);
                MMA16816(acc[1][n0], ah[1], bh0);
                MMA16816(acc[1][n1], ah[1], bh1);
                MMA16816(acc[0][n0], ah[0], bl0);
                MMA16816(acc[0][n1], ah[0], bl1);
                MMA16816(acc[1][n0], ah[1], bl0);
                MMA16816(acc[1][n1], ah[1], bl1);
                MMA16816(acc[0][n0], al[0], bh0);
                MMA16816(acc[0][n1], al[0], bh1);
                MMA16816(acc[1][n0], al[1], bh0);
                MMA16816(acc[1][n1], al[1], bh1);
            }
        }
        if (c + NSTAGE - 1 < NCHUNK) load_chunk((c + 2) % NSTAGE, (c + 2) * 32);

        // interleaved attn normalize: 8 rows per chunk, 256 rows total
        if (attn4) {
            #pragma unroll 2
            for (int i = 0; i < 8; i++) {
                int r = row0 + c * 8 + i;
                float inv = rowinv[r];
                size_t idx = (size_t)r * 256 + tid;
                float4 v = attn4[idx];
                v.x *= inv; v.y *= inv; v.z *= inv; v.w *= inv;
                attn4[idx] = v;
            }
        }
    }

    #pragma unroll
    for (int mf = 0; mf < 2; mf++) {
        int row = ctaM + wm * 32 + mf * 16 + (lane >> 2);
        #pragma unroll
        for (int nf = 0; nf < 8; nf++) {
            int col = ctaN + wn * 64 + nf * 8 + (lane & 3) * 2;
            float bx = bias[col], by = bias[col + 1];
            float2 v0 = {acc[mf][nf][0] + bx, acc[mf][nf][1] + by};
            float2 v1 = {acc[mf][nf][2] + bx, acc[mf][nf][3] + by};
            *(float2*)&C[(size_t)row * Dn + col] = v0;
            *(float2*)&C[(size_t)(row + 8) * Dn + col] = v1;
        }
    }
}

// ---------------------------------------------------------------------------
// Flash-style attention (R10 version — measured best): CTA = (64-query tile,
// b*h), 8 warps, 2 CTAs/SM, single pass, P reused as A-fragments.
// ---------------------------------------------------------------------------
#define KSTRIDE 144
#define APLANE (64 * KSTRIDE)              // 9216 per plane (64 rows)
#define OFF_Q   0
#define OFF_STG (2 * APLANE)               // 18432
#define ASTGB  (4 * APLANE)                // 36864 per stage
#define OFF_MASK (OFF_STG + 2 * ASTGB)     // 92160
#define OFF_PART (OFF_MASK + 4096)         // 96256
#define OFF_INV  (OFF_PART + 512)          // 96768
#define SMEM_ATTN (OFF_INV + 256)          // 97024

__global__ __launch_bounds__(256, 2) void attn_flash(
    const __nv_bfloat16* __restrict__ qhi, const __nv_bfloat16* __restrict__ qlo,
    const __nv_bfloat16* __restrict__ khi, const __nv_bfloat16* __restrict__ klo,
    const __nv_bfloat16* __restrict__ vhi, const __nv_bfloat16* __restrict__ vlo,
    const int* __restrict__ mask, float* __restrict__ attn,
    __nv_bfloat16* __restrict__ hhi, __nv_bfloat16* __restrict__ hlo)
{
    extern __shared__ char smem[];
    const uint32_t sb = smem_u32(smem);
    const int tid = threadIdx.x, wid = tid >> 5, lane = tid & 31;
    const int q8 = lane >> 3, l8 = lane & 7;
    const int wm = wid & 3, wn = wid >> 2;
    const int bh = blockIdx.y, b = bh >> 4, h = bh & 15;
    const int q0 = blockIdx.x * 64;
    const size_t head_base = (size_t)bh * Nn * DHn;

    auto load_tile = [&](int tile, int s) {
        uint32_t stg = sb + OFF_STG + s * ASTGB;
        const __nv_bfloat16* planes[4] = {khi, klo, vhi, vlo};
        #pragma unroll
        for (int i = tid; i < 2048; i += 256) {
            int pl = i >> 9, r = (i >> 3) & 63, c = i & 7;
            const __nv_bfloat16* src = planes[pl] + head_base +
                                       (size_t)(tile * 64 + r) * 64 + c * 8;
            uint32_t dst = stg + pl * APLANE + r * KSTRIDE + c * 16;
            CP_ASYNC16(dst, __cvta_generic_to_global(src));
        }
        CP_COMMIT();
    };

    #pragma unroll
    for (int i = tid; i < 1024; i += 256) {
        int pl = i >> 9, r = (i >> 3) & 63, c = i & 7;
        const __nv_bfloat16* src = (pl ? qlo : qhi) + head_base +
                                   (size_t)(q0 + r) * 64 + c * 8;
        uint32_t dst = sb + OFF_Q + pl * APLANE + r * KSTRIDE + c * 16;
        CP_ASYNC16(dst, __cvta_generic_to_global(src));
    }
    CP_COMMIT();
    load_tile(0, 0);
    load_tile(1, 1);

    {
        int4 mv = ((const int4*)(mask + b * Nn))[tid];
        float4 f = make_float4(mv.x ? 1.f : 0.f, mv.y ? 1.f : 0.f,
                               mv.z ? 1.f : 0.f, mv.w ? 1.f : 0.f);
        ((float4*)(smem + OFF_MASK))[tid] = f;
    }

    uint32_t qfh[4][4], qfl[4][4];
    CP_WAIT2();
    __syncthreads();
    {
        uint32_t qhb = sb + OFF_Q, qlb = sb + OFF_Q + APLANE;
        #pragma unroll
        for (int kk = 0; kk < 4; kk++) {
            uint32_t ao = (uint32_t)((wm * 16 + (q8 & 1) * 8 + l8) * KSTRIDE +
                                     (q8 >> 1) * 16 + kk * 32);
            LDSM_X4(qfh[kk][0], qfh[kk][1], qfh[kk][2], qfh[kk][3], qhb + ao);
            LDSM_X4(qfl[kk][0], qfl[kk][1], qfl[kk][2], qfl[kk][3], qlb + ao);
        }
    }

    const float* mskf = (const float*)(smem + OFF_MASK);
    const int r0 = wm * 16 + (lane >> 2);
    float sum0 = 0.f, sum1 = 0.f;

    float oacc[8][4];
    #pragma unroll
    for (int i = 0; i < 8; i++)
        #pragma unroll
        for (int j = 0; j < 4; j++) oacc[i][j] = 0.f;

    float* attn_row = attn ? attn + ((size_t)bh * Nn + q0 + r0) * Nn : nullptr;

    for (int kt = 0; kt < 16; kt++) {
        if (kt == 15) CP_WAIT0(); else CP_WAIT1();
        __syncthreads();
        uint32_t stg = sb + OFF_STG + (kt & 1) * ASTGB;
        uint32_t khb = stg, klb = stg + APLANE;
        uint32_t vhb = stg + 2 * APLANE, vlb = stg + 3 * APLANE;

        float acc[4][4];
        #pragma unroll
        for (int i = 0; i < 4; i++)
            #pragma unroll
            for (int j = 0; j < 4; j++) acc[i][j] = 0.f;

        #pragma unroll
        for (int kk = 0; kk < 4; kk++) {
            uint32_t bfh[4][2], bfl[4][2];
            #pragma unroll
            for (int pr = 0; pr < 2; pr++) {
                uint32_t bo = (uint32_t)((wn * 32 + pr * 16 + (q8 >> 1) * 8 + l8) * KSTRIDE +
                                         (q8 & 1) * 16 + kk * 32);
                LDSM_X4(bfh[2*pr][0], bfh[2*pr][1], bfh[2*pr+1][0], bfh[2*pr+1][1], khb + bo);
                LDSM_X4(bfl[2*pr][0], bfl[2*pr][1], bfl[2*pr+1][0], bfl[2*pr+1][1], klb + bo);
            }
            #pragma unroll
            for (int nf = 0; nf < 4; nf++) MMA16816(acc[nf], qfh[kk], bfh[nf]);
            #pragma unroll
            for (int nf = 0; nf < 4; nf++) MMA16816(acc[nf], qfh[kk], bfl[nf]);
            #pragma unroll
            for (int nf = 0; nf < 4; nf++) MMA16816(acc[nf], qfl[kk], bfh[nf]);
        }

        #pragma unroll
        for (int nf = 0; nf < 4; nf++) {
            int col = kt * 64 + wn * 32 + nf * 8 + (lane & 3) * 2;
            float2 mv = *(const float2*)&mskf[col];
            acc[nf][0] = __expf(acc[nf][0]) * mv.x;
            acc[nf][1] = __expf(acc[nf][1]) * mv.y;
            acc[nf][2] = __expf(acc[nf][2]) * mv.x;
            acc[nf][3] = __expf(acc[nf][3]) * mv.y;
            sum0 += acc[nf][0] + acc[nf][1];
            sum1 += acc[nf][2] + acc[nf][3];
            if (attn_row) {
                *(float2*)&attn_row[col] = make_float2(acc[nf][0], acc[nf][1]);
                *(float2*)&attn_row[8 * Nn + col] = make_float2(acc[nf][2], acc[nf][3]);
            }
        }

        uint32_t ah[2][4], al[2][4];
        #pragma unroll
        for (int f = 0; f < 2; f++) {
            ah[f][0] = pack_split(make_float2(acc[2*f][0],   acc[2*f][1]),   al[f][0]);
            ah[f][1] = pack_split(make_float2(acc[2*f][2],   acc[2*f][3]),   al[f][1]);
            ah[f][2] = pack_split(make_float2(acc[2*f+1][0], acc[2*f+1][1]), al[f][2]);
            ah[f][3] = pack_split(make_float2(acc[2*f+1][2], acc[2*f+1][3]), al[f][3]);
        }

        #pragma unroll
        for (int f = 0; f < 2; f++) {
            #pragma unroll
            for (int dq = 0; dq < 4; dq++) {
                uint32_t vo = (uint32_t)((wn * 32 + f * 16 + (q8 & 1) * 8 + l8) * KSTRIDE +
                                         dq * 32 + (q8 >> 1) * 16);
                uint32_t vh0[2], vh1[2], vl0[2], vl1[2];
                LDSM_X4_T(vh0[0], vh0[1], vh1[0], vh1[1], vhb + vo);
                LDSM_X4_T(vl0[0], vl0[1], vl1[0], vl1[1], vlb + vo);
                MMA16816(oacc[2*dq],     ah[f], vh0);
                MMA16816(oacc[2*dq + 1], ah[f], vh1);
                MMA16816(oacc[2*dq],     ah[f], vl0);
                MMA16816(oacc[2*dq + 1], ah[f], vl1);
                MMA16816(oacc[2*dq],     al[f], vh0);
                MMA16816(oacc[2*dq + 1], al[f], vh1);
            }
        }

        __syncthreads();
        if (kt + 2 < 16) load_tile(kt + 2, kt & 1);
    }

    sum0 += __shfl_xor_sync(0xffffffffu, sum0, 1);
    sum0 += __shfl_xor_sync(0xffffffffu, sum0, 2);
    sum1 += __shfl_xor_sync(0xffffffffu, sum1, 1);
    sum1 += __shfl_xor_sync(0xffffffffu, sum1, 2);
    {
        float* part = (float*)(smem + OFF_PART);
        if ((lane & 3) == 0) {
            part[wn * 64 + r0]     = sum0;
            part[wn * 64 + r0 + 8] = sum1;
        }
    }
    {
        uint32_t slot = sb + OFF_STG + wid * 4096;
        #pragma unroll
        for (int nt = 0; nt < 8; nt++) {
            uint32_t a0 = slot + (uint32_t)(lane >> 2) * 256 + (nt * 8 + (lane & 3) * 2) * 4;
            *(float2*)(smem + (a0 - sb)) = make_float2(oacc[nt][0], oacc[nt][1]);
            *(float2*)(smem + (a0 - sb) + 8 * 256) = make_float2(oacc[nt][2], oacc[nt][3]);
        }
    }
    __syncthreads();
    {
        const float* part = (const float*)(smem + OFF_PART);
        float* invs = (float*)(smem + OFF_INV);
        if (tid < 64) {
            float inv = 1.f / (part[tid] + part[64 + tid]);
            invs[tid] = inv;
            if (attn) g_rowinv[(size_t)bh * Nn + q0 + tid] = inv;
        }
    }
    __syncthreads();

    {
        const float* invs = (const float*)(smem + OFF_INV);
        int r = wid * 8 + (lane >> 2);
        int c0 = (lane & 3) * 16;
        int strip = r >> 4, rl = r & 15;
        const float* s0 = (const float*)(smem + OFF_STG + strip * 4096) + rl * 64 + c0;
        const float* s1 = (const float*)(smem + OFF_STG + (strip + 4) * 4096) + rl * 64 + c0;
        float inv = invs[r];
        size_t dbase = ((size_t)(b * Nn) + q0 + r) * Dn + h * 64 + c0;
        #pragma unroll
        for (int c = 0; c < 16; c += 2) {
            float v0 = (s0[c]     + s1[c])     * inv;
            float v1 = (s0[c + 1] + s1[c + 1]) * inv;
            uint32_t lo;
            uint32_t hi = pack_split(make_float2(v0, v1), lo);
            *(uint32_t*)&hhi[dbase + c] = hi;
            *(uint32_t*)&hlo[dbase + c] = lo;
        }
    }
}

// ---------------------------------------------------------------------------

extern "C" void kernel_launch(void* const* d_in, const int* in_sizes, int n_in,
                              void* d_out, int out_size)
{
    const float* x     = (const float*)d_in[0];
    const int*   mask  = (const int*)d_in[1];
    const float* w_qkv = (const float*)d_in[2];
    const float* w_out = (const float*)d_in[3];
    const float* b_out = (const float*)d_in[4];

    float* out = (float*)d_out;
    const size_t out_elems  = (size_t)Bn * Nn * Dn;
    const size_t attn_elems = (size_t)Bn * Hn * Nn * Nn;
    float* attn = ((size_t)out_size >= out_elems + attn_elems) ? out + out_elems : nullptr;

    __nv_bfloat16 *xhi, *xlo, *wqkvThi, *wqkvTlo, *woutThi, *woutTlo, *hhi, *hlo;
    __nv_bfloat16 *qhi, *qlo, *khi, *klo, *vhi, *vlo;
    float* rowinv;
    cudaGetSymbolAddress((void**)&xhi, g_xhi);
    cudaGetSymbolAddress((void**)&xlo, g_xlo);
    cudaGetSymbolAddress((void**)&wqkvThi, g_wqkvThi);
    cudaGetSymbolAddress((void**)&wqkvTlo, g_wqkvTlo);
    cudaGetSymbolAddress((void**)&woutThi, g_woutThi);
    cudaGetSymbolAddress((void**)&woutTlo, g_woutTlo);
    cudaGetSymbolAddress((void**)&hhi, g_hhi);
    cudaGetSymbolAddress((void**)&hlo, g_hlo);
    cudaGetSymbolAddress((void**)&qhi, g_qhi);
    cudaGetSymbolAddress((void**)&qlo, g_qlo);
    cudaGetSymbolAddress((void**)&khi, g_khi);
    cudaGetSymbolAddress((void**)&klo, g_klo);
    cudaGetSymbolAddress((void**)&vhi, g_vhi);
    cudaGetSymbolAddress((void**)&vlo, g_vlo);
    cudaGetSymbolAddress((void**)&rowinv, g_rowinv);

    cudaFuncSetAttribute(gemm_qkv, cudaFuncAttributeMaxDynamicSharedMemorySize, SMEM_GEMM);
    cudaFuncSetAttribute(gemm_out, cudaFuncAttributeMaxDynamicSharedMemorySize, SMEM_GEMM);
    cudaFuncSetAttribute(attn_flash, cudaFuncAttributeMaxDynamicSharedMemorySize, SMEM_ATTN);

    const int n4x = (Bn * Nn * Dn) / 4;

    // 1) splits
    split_kernel<<<(n4x + 255) / 256, 256>>>((const float4*)x,
                                             (__nv_bfloat162*)xhi, (__nv_bfloat162*)xlo, n4x);
    splitT_kernel<<<dim3(D3 / 32, Dn / 32), dim3(32, 8)>>>(w_qkv, wqkvThi, wqkvTlo, Dn, D3);
    splitT_kernel<<<dim3(Dn / 32, Dn / 32), dim3(32, 8)>>>(w_out, woutThi, woutTlo, Dn, Dn);

    // 2) QKV projection, fused split into per-head q/k/v hi/lo
    gemm_qkv<<<dim3(D3 / 128, (Bn * Nn) / 128), 256, SMEM_GEMM>>>(
        xhi, xlo, wqkvThi, wqkvTlo, qhi, qlo, khi, klo, vhi, vlo);

    // 3) flash attention (writes unnormalized attn + rowinv + hhi/hlo)
    attn_flash<<<dim3(Nn / 64, Bn * Hn), 256, SMEM_ATTN>>>(
        qhi, qlo, khi, klo, vhi, vlo, mask, attn, hhi, hlo);

    // 4) output projection with bias + interleaved attn normalize
    gemm_out<<<dim3(Dn / 128, (Bn * Nn) / 128), 256, SMEM_GEMM>>>(
        hhi, hlo, woutThi, woutTlo, out, b_out,
        (float4*)attn, rowinv);
}

// round 14
// speedup vs baseline: 1.1222x; 1.1222x over previous
#include <cuda_runtime.h>
#include <cuda_bf16.h>
#include <cstdint>

// Problem constants
#define Bn 8
#define Nn 1024
#define Dn 1024
#define Hn 16
#define DHn 64
#define D3 3072
#define Kdim 1024

// ---------------------------------------------------------------------------
// Device scratch (allocation-free)
// ---------------------------------------------------------------------------
__device__ __nv_bfloat16 g_xhi[(size_t)Bn * Nn * Dn];
__device__ __nv_bfloat16 g_xlo[(size_t)Bn * Nn * Dn];
__device__ __nv_bfloat16 g_wqkvThi[(size_t)D3 * Dn];
__device__ __nv_bfloat16 g_wqkvTlo[(size_t)D3 * Dn];
__device__ __nv_bfloat16 g_woutThi[(size_t)Dn * Dn];
__device__ __nv_bfloat16 g_woutTlo[(size_t)Dn * Dn];
__device__ __nv_bfloat16 g_hhi[(size_t)Bn * Nn * Dn];
__device__ __nv_bfloat16 g_hlo[(size_t)Bn * Nn * Dn];
#define HEADELEMS ((size_t)Bn * Hn * Nn * DHn)
__device__ __nv_bfloat16 g_qhi[HEADELEMS];
__device__ __nv_bfloat16 g_qlo[HEADELEMS];
__device__ __nv_bfloat16 g_khi[HEADELEMS];
__device__ __nv_bfloat16 g_klo[HEADELEMS];
__device__ __nv_bfloat16 g_vhi[HEADELEMS];
__device__ __nv_bfloat16 g_vlo[HEADELEMS];
__device__ float g_rowinv[(size_t)Bn * Hn * Nn];   // 1/rowsum per (b,h,q)

// ---------------------------------------------------------------------------
// PTX helpers (baseline sm_80+ features only)
// ---------------------------------------------------------------------------
__device__ __forceinline__ uint32_t smem_u32(const void* p) {
    uint32_t a;
    asm("{ .reg .u64 t; cvta.to.shared.u64 t, %1; cvt.u32.u64 %0, t; }"
        : "=r"(a) : "l"(p));
    return a;
}

#define CP_ASYNC16(dst, gsrc) \
    asm volatile("cp.async.cg.shared.global [%0], [%1], 16;" :: "r"(dst), "l"(gsrc))
#define CP_COMMIT() asm volatile("cp.async.commit_group;" ::: "memory")
#define CP_WAIT2()  asm volatile("cp.async.wait_group 2;" ::: "memory")
#define CP_WAIT1()  asm volatile("cp.async.wait_group 1;" ::: "memory")
#define CP_WAIT0()  asm volatile("cp.async.wait_group 0;" ::: "memory")

#define LDSM_X4(r0, r1, r2, r3, addr) \
    asm volatile("ldmatrix.sync.aligned.m8n8.x4.shared.b16 {%0,%1,%2,%3}, [%4];" \
                 : "=r"(r0), "=r"(r1), "=r"(r2), "=r"(r3) : "r"(addr))

#define LDSM_X4_T(r0, r1, r2, r3, addr) \
    asm volatile("ldmatrix.sync.aligned.m8n8.x4.trans.shared.b16 {%0,%1,%2,%3}, [%4];" \
                 : "=r"(r0), "=r"(r1), "=r"(r2), "=r"(r3) : "r"(addr))

#define MMA16816(d, a, b) \
    asm volatile("mma.sync.aligned.m16n8k16.row.col.f32.bf16.bf16.f32 " \
                 "{%0,%1,%2,%3}, {%4,%5,%6,%7}, {%8,%9}, {%0,%1,%2,%3};" \
                 : "+f"((d)[0]), "+f"((d)[1]), "+f"((d)[2]), "+f"((d)[3]) \
                 : "r"((a)[0]), "r"((a)[1]), "r"((a)[2]), "r"((a)[3]), \
                   "r"((b)[0]), "r"((b)[1]))

__device__ __forceinline__ uint32_t pack_split(float2 p, uint32_t& lo) {
    __nv_bfloat16 hx = __float2bfloat16(p.x), hy = __float2bfloat16(p.y);
    __nv_bfloat16 lx = __float2bfloat16(p.x - __bfloat162float(hx));
    __nv_bfloat16 ly = __float2bfloat16(p.y - __bfloat162float(hy));
    __nv_bfloat162 hv = __halves2bfloat162(hx, hy);
    __nv_bfloat162 lv = __halves2bfloat162(lx, ly);
    lo = *(uint32_t*)&lv;
    return *(uint32_t*)&hv;
}

// swizzled address in a 64B-row tile (gemm): chunk c ^ ((row>>1)&3)
#define SWADDR(base, row, c) \
    ((base) + (uint32_t)(row) * 64u + ((uint32_t)((c) ^ (((row) >> 1) & 3)) << 4))

// ---------------------------------------------------------------------------
// Split kernels
// ---------------------------------------------------------------------------
__global__ __launch_bounds__(256) void split_kernel(
    const float4* __restrict__ in, __nv_bfloat162* __restrict__ hi,
    __nv_bfloat162* __restrict__ lo, int n4)
{
    int i = blockIdx.x * 256 + threadIdx.x;
    if (i >= n4) return;
    float4 v = in[i];
    __nv_bfloat16 h0 = __float2bfloat16(v.x), h1 = __float2bfloat16(v.y);
    __nv_bfloat16 h2 = __float2bfloat16(v.z), h3 = __float2bfloat16(v.w);
    __nv_bfloat16 l0 = __float2bfloat16(v.x - __bfloat162float(h0));
    __nv_bfloat16 l1 = __float2bfloat16(v.y - __bfloat162float(h1));
    __nv_bfloat16 l2 = __float2bfloat16(v.z - __bfloat162float(h2));
    __nv_bfloat16 l3 = __float2bfloat16(v.w - __bfloat162float(h3));
    hi[2 * i]     = __halves2bfloat162(h0, h1);
    hi[2 * i + 1] = __halves2bfloat162(h2, h3);
    lo[2 * i]     = __halves2bfloat162(l0, l1);
    lo[2 * i + 1] = __halves2bfloat162(l2, l3);
}

__global__ __launch_bounds__(256) void splitT_kernel(
    const float* __restrict__ in, __nv_bfloat16* __restrict__ hiT,
    __nv_bfloat16* __restrict__ loT, int R, int C)
{
    __shared__ float t[32][33];
    int bx = blockIdx.x * 32;
    int by = blockIdx.y * 32;
    int x = threadIdx.x, y = threadIdx.y;  // 32 x 8
    #pragma unroll
    for (int i = y; i < 32; i += 8)
        t[i][x] = in[(size_t)(by + i) * C + bx + x];
    __syncthreads();
    #pragma unroll
    for (int i = y; i < 32; i += 8) {
        float v = t[x][i];
        __nv_bfloat16 h = __float2bfloat16(v);
        size_t o = (size_t)(bx + i) * R + by + x;
        hiT[o] = h;
        loT[o] = __float2bfloat16(v - __bfloat162float(h));
    }
}

// ---------------------------------------------------------------------------
// bf16-split GEMM, mode 1 (QKV projection + per-head split).
// ---------------------------------------------------------------------------
#define TILEB (128 * 64)
#define STAGEB (4 * TILEB)
#define NSTAGE 3
#define SMEM_GEMM (NSTAGE * STAGEB)    // 98304
#define NCHUNK (Kdim / 32)

__global__ __launch_bounds__(256, 2) void gemm_qkv(
    const __nv_bfloat16* __restrict__ Ahi, const __nv_bfloat16* __restrict__ Alo,
    const __nv_bfloat16* __restrict__ BThi, const __nv_bfloat16* __restrict__ BTlo,
    __nv_bfloat16* __restrict__ qhi, __nv_bfloat16* __restrict__ qlo,
    __nv_bfloat16* __restrict__ khi, __nv_bfloat16* __restrict__ klo,
    __nv_bfloat16* __restrict__ vhi, __nv_bfloat16* __restrict__ vlo)
{
    extern __shared__ char smem[];
    const uint32_t sb = smem_u32(smem);
    const int tid = threadIdx.x, wid = tid >> 5, lane = tid & 31;
    const int wm = wid >> 1;
    const int wn = wid & 1;
    const int ctaM = blockIdx.y * 128, ctaN = blockIdx.x * 128;

    const __nv_bfloat16* gsrc[4] = {
        Ahi + (size_t)ctaM * Kdim, Alo + (size_t)ctaM * Kdim,
        BThi + (size_t)ctaN * Kdim, BTlo + (size_t)ctaN * Kdim};

    auto load_chunk = [&](int s, int k0) {
        uint32_t base = sb + s * STAGEB;
        #pragma unroll
        for (int t = 0; t < 4; t++) {
            uint32_t tb = base + t * TILEB;
            const __nv_bfloat16* g = gsrc[t] + k0;
            #pragma unroll
            for (int i = tid; i < 512; i += 256) {
                int r = i >> 2, c = i & 3;
                uint32_t dst = SWADDR(tb, r, c);
                size_t gs = __cvta_generic_to_global(g + (size_t)r * Kdim + c * 8);
                CP_ASYNC16(dst, gs);
            }
        }
        CP_COMMIT();
    };

    float acc[2][8][4];
    #pragma unroll
    for (int i = 0; i < 2; i++)
        #pragma unroll
        for (int j = 0; j < 8; j++)
            #pragma unroll
            for (int k = 0; k < 4; k++) acc[i][j][k] = 0.f;

    load_chunk(0, 0);
    load_chunk(1, 32);

    const int q = lane >> 3, l8 = lane & 7;
    const int arow = wm * 32 + (q & 1) * 8 + l8;
    const int brow = wn * 64 + (q >> 1) * 8 + l8;
    const int acsel = q >> 1;
    const int bcsel = q & 1;

    for (int c = 0; c < NCHUNK; c++) {
        int s = c % NSTAGE;
        if (c == NCHUNK - 1) CP_WAIT0(); else CP_WAIT1();
        __syncthreads();

        uint32_t base = sb + s * STAGEB;
        uint32_t tAh = base, tAl = base + TILEB;
        uint32_t tBh = base + 2 * TILEB, tBl = base + 3 * TILEB;

        #pragma unroll
        for (int kk = 0; kk < 2; kk++) {
            int ca = kk * 2 + acsel;
            int cb = kk * 2 + bcsel;
            uint32_t ah[2][4], al[2][4];
            #pragma unroll
            for (int mf = 0; mf < 2; mf++) {
                int row = arow + mf * 16;
                LDSM_X4(ah[mf][0], ah[mf][1], ah[mf][2], ah[mf][3], SWADDR(tAh, row, ca));
                LDSM_X4(al[mf][0], al[mf][1], al[mf][2], al[mf][3], SWADDR(tAl, row, ca));
            }
            #pragma unroll
            for (int nf2 = 0; nf2 < 4; nf2++) {
                uint32_t bh0[2], bh1[2], bl0[2], bl1[2];
                int row = brow + nf2 * 16;
                LDSM_X4(bh0[0], bh0[1], bh1[0], bh1[1], SWADDR(tBh, row, cb));
                LDSM_X4(bl0[0], bl0[1], bl1[0], bl1[1], SWADDR(tBl, row, cb));
                int n0 = 2 * nf2, n1 = 2 * nf2 + 1;
                MMA16816(acc[0][n0], ah[0], bh0);
                MMA16816(acc[0][n1], ah[0], bh1);
                MMA16816(acc[1][n0], ah[1], bh0);
                MMA16816(acc[1][n1], ah[1], bh1);
                MMA16816(acc[0][n0], ah[0], bl0);
                MMA16816(acc[0][n1], ah[0], bl1);
                MMA16816(acc[1][n0], ah[1], bl0);
                MMA16816(acc[1][n1], ah[1], bl1);
                MMA16816(acc[0][n0], al[0], bh0);
                MMA16816(acc[0][n1], al[0], bh1);
                MMA16816(acc[1][n0], al[1], bh0);
                MMA16816(acc[1][n1], al[1], bh1);
            }
        }
        if (c + NSTAGE - 1 < NCHUNK) load_chunk((c + 2) % NSTAGE, (c + 2) * 32);
    }

    #pragma unroll
    for (int mf = 0; mf < 2; mf++) {
        int row = ctaM + wm * 32 + mf * 16 + (lane >> 2);
        int b = row >> 10, n = row & 1023;
        #pragma unroll
        for (int nf = 0; nf < 8; nf++) {
            int col = ctaN + wn * 64 + nf * 8 + (lane & 3) * 2;
            int s = col >> 10, hh = (col >> 6) & 15, dh = col & 63;
            float sc = (s == 0) ? 0.125f : 1.0f;
            __nv_bfloat16* hiP = (s == 0) ? qhi : (s == 1) ? khi : vhi;
            __nv_bfloat16* loP = (s == 0) ? qlo : (s == 1) ? klo : vlo;
            size_t o0 = (((size_t)(b * 16 + hh)) * 1024 + n) * 64 + dh;
            size_t o1 = o0 + 8 * 64;
            uint32_t lo;
            uint32_t hi = pack_split(
                make_float2(acc[mf][nf][0] * sc, acc[mf][nf][1] * sc), lo);
            *(uint32_t*)&hiP[o0] = hi;
            *(uint32_t*)&loP[o0] = lo;
            hi = pack_split(
                make_float2(acc[mf][nf][2] * sc, acc[mf][nf][3] * sc), lo);
            *(uint32_t*)&hiP[o1] = hi;
            *(uint32_t*)&loP[o1] = lo;
        }
    }
}

// ---------------------------------------------------------------------------
// bf16-split GEMM, mode 0 (output projection + bias) — clean, no norm logic.
// ---------------------------------------------------------------------------
__global__ __launch_bounds__(256, 2) void gemm_out(
    const __nv_bfloat16* __restrict__ Ahi, const __nv_bfloat16* __restrict__ Alo,
    const __nv_bfloat16* __restrict__ BThi, const __nv_bfloat16* __restrict__ BTlo,
    float* __restrict__ C, const float* __restrict__ bias)
{
    extern __shared__ char smem[];
    const uint32_t sb = smem_u32(smem);
    const int tid = threadIdx.x, wid = tid >> 5, lane = tid & 31;
    const int wm = wid >> 1;
    const int wn = wid & 1;
    const int ctaM = blockIdx.y * 128, ctaN = blockIdx.x * 128;

    const __nv_bfloat16* gsrc[4] = {
        Ahi + (size_t)ctaM * Kdim, Alo + (size_t)ctaM * Kdim,
        BThi + (size_t)ctaN * Kdim, BTlo + (size_t)ctaN * Kdim};

    auto load_chunk = [&](int s, int k0) {
        uint32_t base = sb + s * STAGEB;
        #pragma unroll
        for (int t = 0; t < 4; t++) {
            uint32_t tb = base + t * TILEB;
            const __nv_bfloat16* g = gsrc[t] + k0;
            #pragma unroll
            for (int i = tid; i < 512; i += 256) {
                int r = i >> 2, c = i & 3;
                uint32_t dst = SWADDR(tb, r, c);
                size_t gs = __cvta_generic_to_global(g + (size_t)r * Kdim + c * 8);
                CP_ASYNC16(dst, gs);
            }
        }
        CP_COMMIT();
    };

    float acc[2][8][4];
    #pragma unroll
    for (int i = 0; i < 2; i++)
        #pragma unroll
        for (int j = 0; j < 8; j++)
            #pragma unroll
            for (int k = 0; k < 4; k++) acc[i][j][k] = 0.f;

    load_chunk(0, 0);
    load_chunk(1, 32);

    const int q = lane >> 3, l8 = lane & 7;
    const int arow = wm * 32 + (q & 1) * 8 + l8;
    const int brow = wn * 64 + (q >> 1) * 8 + l8;
    const int acsel = q >> 1;
    const int bcsel = q & 1;

    for (int c = 0; c < NCHUNK; c++) {
        int s = c % NSTAGE;
        if (c == NCHUNK - 1) CP_WAIT0(); else CP_WAIT1();
        __syncthreads();

        uint32_t base = sb + s * STAGEB;
        uint32_t tAh = base, tAl = base + TILEB;
        uint32_t tBh = base + 2 * TILEB, tBl = base + 3 * TILEB;

        #pragma unroll
        for (int kk = 0; kk < 2; kk++) {
            int ca = kk * 2 + acsel;
            int cb = kk * 2 + bcsel;
            uint32_t ah[2][4], al[2][4];
            #pragma unroll
            for (int mf = 0; mf < 2; mf++) {
                int row = arow + mf * 16;
                LDSM_X4(ah[mf][0], ah[mf][1], ah[mf][2], ah[mf][3], SWADDR(tAh, row, ca));
                LDSM_X4(al[mf][0], al[mf][1], al[mf][2], al[mf][3], SWADDR(tAl, row, ca));
            }
            #pragma unroll
            for (int nf2 = 0; nf2 < 4; nf2++) {
                uint32_t bh0[2], bh1[2], bl0[2], bl1[2];
                int row = brow + nf2 * 16;
                LDSM_X4(bh0[0], bh0[1], bh1[0], bh1[1], SWADDR(tBh, row, cb));
                LDSM_X4(bl0[0], bl0[1], bl1[0], bl1[1], SWADDR(tBl, row, cb));
                int n0 = 2 * nf2, n1 = 2 * nf2 + 1;
                MMA16816(acc[0][n0], ah[0], bh0);
                MMA16816(acc[0][n1], ah[0], bh1);
                MMA16816(acc[1][n0], ah[1], bh0);
                MMA16816(acc[1][n1], ah[1], bh1);
                MMA16816(acc[0][n0], ah[0], bl0);
                MMA16816(acc[0][n1], ah[0], bl1);
                MMA16816(acc[1][n0], ah[1], bl0);
                MMA16816(acc[1][n1], ah[1], bl1);
                MMA16816(acc[0][n0], al[0], bh0);
                MMA16816(acc[0][n1], al[0], bh1);
                MMA16816(acc[1][n0], al[1], bh0);
                MMA16816(acc[1][n1], al[1], bh1);
            }
        }
        if (c + NSTAGE - 1 < NCHUNK) load_chunk((c + 2) % NSTAGE, (c + 2) * 32);
    }

    #pragma unroll
    for (int mf = 0; mf < 2; mf++) {
        int row = ctaM + wm * 32 + mf * 16 + (lane >> 2);
        #pragma unroll
        for (int nf = 0; nf < 8; nf++) {
            int col = ctaN + wn * 64 + nf * 8 + (lane & 3) * 2;
            float bx = bias[col], by = bias[col + 1];
            float2 v0 = {acc[mf][nf][0] + bx, acc[mf][nf][1] + by};
            float2 v1 = {acc[mf][nf][2] + bx, acc[mf][nf][3] + by};
            *(float2*)&C[(size_t)row * Dn + col] = v0;
            *(float2*)&C[(size_t)(row + 8) * Dn + col] = v1;
        }
    }
}

// ---------------------------------------------------------------------------
// Normalize attn in place (0 smem — co-resides with gemm_out on the same SMs
// via a forked stream in the captured graph).
// ---------------------------------------------------------------------------
__global__ __launch_bounds__(256) void norm_attn(float4* __restrict__ attn4,
                                                 const float* __restrict__ rowinv)
{
    int idx = blockIdx.x * 256 + threadIdx.x;
    float inv = rowinv[idx >> 8];
    float4 v = attn4[idx];
    v.x *= inv; v.y *= inv; v.z *= inv; v.w *= inv;
    attn4[idx] = v;
}

// ---------------------------------------------------------------------------
// Flash-style attention (R10 version — measured best).
// ---------------------------------------------------------------------------
#define KSTRIDE 144
#define APLANE (64 * KSTRIDE)
#define OFF_Q   0
#define OFF_STG (2 * APLANE)
#define ASTGB  (4 * APLANE)
#define OFF_MASK (OFF_STG + 2 * ASTGB)
#define OFF_PART (OFF_MASK + 4096)
#define OFF_INV  (OFF_PART + 512)
#define SMEM_ATTN (OFF_INV + 256)          // 97024

__global__ __launch_bounds__(256, 2) void attn_flash(
    const __nv_bfloat16* __restrict__ qhi, const __nv_bfloat16* __restrict__ qlo,
    const __nv_bfloat16* __restrict__ khi, const __nv_bfloat16* __restrict__ klo,
    const __nv_bfloat16* __restrict__ vhi, const __nv_bfloat16* __restrict__ vlo,
    const int* __restrict__ mask, float* __restrict__ attn,
    __nv_bfloat16* __restrict__ hhi, __nv_bfloat16* __restrict__ hlo)
{
    extern __shared__ char smem[];
    const uint32_t sb = smem_u32(smem);
    const int tid = threadIdx.x, wid = tid >> 5, lane = tid & 31;
    const int q8 = lane >> 3, l8 = lane & 7;
    const int wm = wid & 3, wn = wid >> 2;
    const int bh = blockIdx.y, b = bh >> 4, h = bh & 15;
    const int q0 = blockIdx.x * 64;
    const size_t head_base = (size_t)bh * Nn * DHn;

    auto load_tile = [&](int tile, int s) {
        uint32_t stg = sb + OFF_STG + s * ASTGB;
        const __nv_bfloat16* planes[4] = {khi, klo, vhi, vlo};
        #pragma unroll
        for (int i = tid; i < 2048; i += 256) {
            int pl = i >> 9, r = (i >> 3) & 63, c = i & 7;
            const __nv_bfloat16* src = planes[pl] + head_base +
                                       (size_t)(tile * 64 + r) * 64 + c * 8;
            uint32_t dst = stg + pl * APLANE + r * KSTRIDE + c * 16;
            CP_ASYNC16(dst, __cvta_generic_to_global(src));
        }
        CP_COMMIT();
    };

    #pragma unroll
    for (int i = tid; i < 1024; i += 256) {
        int pl = i >> 9, r = (i >> 3) & 63, c = i & 7;
        const __nv_bfloat16* src = (pl ? qlo : qhi) + head_base +
                                   (size_t)(q0 + r) * 64 + c * 8;
        uint32_t dst = sb + OFF_Q + pl * APLANE + r * KSTRIDE + c * 16;
        CP_ASYNC16(dst, __cvta_generic_to_global(src));
    }
    CP_COMMIT();
    load_tile(0, 0);
    load_tile(1, 1);

    {
        int4 mv = ((const int4*)(mask + b * Nn))[tid];
        float4 f = make_float4(mv.x ? 1.f : 0.f, mv.y ? 1.f : 0.f,
                               mv.z ? 1.f : 0.f, mv.w ? 1.f : 0.f);
        ((float4*)(smem + OFF_MASK))[tid] = f;
    }

    uint32_t qfh[4][4], qfl[4][4];
    CP_WAIT2();
    __syncthreads();
    {
        uint32_t qhb = sb + OFF_Q, qlb = sb + OFF_Q + APLANE;
        #pragma unroll
        for (int kk = 0; kk < 4; kk++) {
            uint32_t ao = (uint32_t)((wm * 16 + (q8 & 1) * 8 + l8) * KSTRIDE +
                                     (q8 >> 1) * 16 + kk * 32);
            LDSM_X4(qfh[kk][0], qfh[kk][1], qfh[kk][2], qfh[kk][3], qhb + ao);
            LDSM_X4(qfl[kk][0], qfl[kk][1], qfl[kk][2], qfl[kk][3], qlb + ao);
        }
    }

    const float* mskf = (const float*)(smem + OFF_MASK);
    const int r0 = wm * 16 + (lane >> 2);
    float sum0 = 0.f, sum1 = 0.f;

    float oacc[8][4];
    #pragma unroll
    for (int i = 0; i < 8; i++)
        #pragma unroll
        for (int j = 0; j < 4; j++) oacc[i][j] = 0.f;

    float* attn_row = attn ? attn + ((size_t)bh * Nn + q0 + r0) * Nn : nullptr;

    for (int kt = 0; kt < 16; kt++) {
        if (kt == 15) CP_WAIT0(); else CP_WAIT1();
        __syncthreads();
        uint32_t stg = sb + OFF_STG + (kt & 1) * ASTGB;
        uint32_t khb = stg, klb = stg + APLANE;
        uint32_t vhb = stg + 2 * APLANE, vlb = stg + 3 * APLANE;

        float acc[4][4];
        #pragma unroll
        for (int i = 0; i < 4; i++)
            #pragma unroll
            for (int j = 0; j < 4; j++) acc[i][j] = 0.f;

        #pragma unroll
        for (int kk = 0; kk < 4; kk++) {
            uint32_t bfh[4][2], bfl[4][2];
            #pragma unroll
            for (int pr = 0; pr < 2; pr++) {
                uint32_t bo = (uint32_t)((wn * 32 + pr * 16 + (q8 >> 1) * 8 + l8) * KSTRIDE +
                                         (q8 & 1) * 16 + kk * 32);
                LDSM_X4(bfh[2*pr][0], bfh[2*pr][1], bfh[2*pr+1][0], bfh[2*pr+1][1], khb + bo);
                LDSM_X4(bfl[2*pr][0], bfl[2*pr][1], bfl[2*pr+1][0], bfl[2*pr+1][1], klb + bo);
            }
            #pragma unroll
            for (int nf = 0; nf < 4; nf++) MMA16816(acc[nf], qfh[kk], bfh[nf]);
            #pragma unroll
            for (int nf = 0; nf < 4; nf++) MMA16816(acc[nf], qfh[kk], bfl[nf]);
            #pragma unroll
            for (int nf = 0; nf < 4; nf++) MMA16816(acc[nf], qfl[kk], bfh[nf]);
        }

        #pragma unroll
        for (int nf = 0; nf < 4; nf++) {
            int col = kt * 64 + wn * 32 + nf * 8 + (lane & 3) * 2;
            float2 mv = *(const float2*)&mskf[col];
            acc[nf][0] = __expf(acc[nf][0]) * mv.x;
            acc[nf][1] = __expf(acc[nf][1]) * mv.y;
            acc[nf][2] = __expf(acc[nf][2]) * mv.x;
            acc[nf][3] = __expf(acc[nf][3]) * mv.y;
            sum0 += acc[nf][0] + acc[nf][1];
            sum1 += acc[nf][2] + acc[nf][3];
            if (attn_row) {
                *(float2*)&attn_row[col] = make_float2(acc[nf][0], acc[nf][1]);
                *(float2*)&attn_row[8 * Nn + col] = make_float2(acc[nf][2], acc[nf][3]);
            }
        }

        uint32_t ah[2][4], al[2][4];
        #pragma unroll
        for (int f = 0; f < 2; f++) {
            ah[f][0] = pack_split(make_float2(acc[2*f][0],   acc[2*f][1]),   al[f][0]);
            ah[f][1] = pack_split(make_float2(acc[2*f][2],   acc[2*f][3]),   al[f][1]);
            ah[f][2] = pack_split(make_float2(acc[2*f+1][0], acc[2*f+1][1]), al[f][2]);
            ah[f][3] = pack_split(make_float2(acc[2*f+1][2], acc[2*f+1][3]), al[f][3]);
        }

        #pragma unroll
        for (int f = 0; f < 2; f++) {
            #pragma unroll
            for (int dq = 0; dq < 4; dq++) {
                uint32_t vo = (uint32_t)((wn * 32 + f * 16 + (q8 & 1) * 8 + l8) * KSTRIDE +
                                         dq * 32 + (q8 >> 1) * 16);
                uint32_t vh0[2], vh1[2], vl0[2], vl1[2];
                LDSM_X4_T(vh0[0], vh0[1], vh1[0], vh1[1], vhb + vo);
                LDSM_X4_T(vl0[0], vl0[1], vl1[0], vl1[1], vlb + vo);
                MMA16816(oacc[2*dq],     ah[f], vh0);
                MMA16816(oacc[2*dq + 1], ah[f], vh1);
                MMA16816(oacc[2*dq],     ah[f], vl0);
                MMA16816(oacc[2*dq + 1], ah[f], vl1);
                MMA16816(oacc[2*dq],     al[f], vh0);
                MMA16816(oacc[2*dq + 1], al[f], vh1);
            }
        }

        __syncthreads();
        if (kt + 2 < 16) load_tile(kt + 2, kt & 1);
    }

    sum0 += __shfl_xor_sync(0xffffffffu, sum0, 1);
    sum0 += __shfl_xor_sync(0xffffffffu, sum0, 2);
    sum1 += __shfl_xor_sync(0xffffffffu, sum1, 1);
    sum1 += __shfl_xor_sync(0xffffffffu, sum1, 2);
    {
        float* part = (float*)(smem + OFF_PART);
        if ((lane & 3) == 0) {
            part[wn * 64 + r0]     = sum0;
            part[wn * 64 + r0 + 8] = sum1;
        }
    }
    {
        uint32_t slot = sb + OFF_STG + wid * 4096;
        #pragma unroll
        for (int nt = 0; nt < 8; nt++) {
            uint32_t a0 = slot + (uint32_t)(lane >> 2) * 256 + (nt * 8 + (lane & 3) * 2) * 4;
            *(float2*)(smem + (a0 - sb)) = make_float2(oacc[nt][0], oacc[nt][1]);
            *(float2*)(smem + (a0 - sb) + 8 * 256) = make_float2(oacc[nt][2], oacc[nt][3]);
        }
    }
    __syncthreads();
    {
        const float* part = (const float*)(smem + OFF_PART);
        float* invs = (float*)(smem + OFF_INV);
        if (tid < 64) {
            float inv = 1.f / (part[tid] + part[64 + tid]);
            invs[tid] = inv;
            if (attn) g_rowinv[(size_t)bh * Nn + q0 + tid] = inv;
        }
    }
    __syncthreads();

    {
        const float* invs = (const float*)(smem + OFF_INV);
        int r = wid * 8 + (lane >> 2);
        int c0 = (lane & 3) * 16;
        int strip = r >> 4, rl = r & 15;
        const float* s0 = (const float*)(smem + OFF_STG + strip * 4096) + rl * 64 + c0;
        const float* s1 = (const float*)(smem + OFF_STG + (strip + 4) * 4096) + rl * 64 + c0;
        float inv = invs[r];
        size_t dbase = ((size_t)(b * Nn) + q0 + r) * Dn + h * 64 + c0;
        #pragma unroll
        for (int c = 0; c < 16; c += 2) {
            float v0 = (s0[c]     + s1[c])     * inv;
            float v1 = (s0[c + 1] + s1[c + 1]) * inv;
            uint32_t lo;
            uint32_t hi = pack_split(make_float2(v0, v1), lo);
            *(uint32_t*)&hhi[dbase + c] = hi;
            *(uint32_t*)&hlo[dbase + c] = lo;
        }
    }
}

// ---------------------------------------------------------------------------

extern "C" void kernel_launch(void* const* d_in, const int* in_sizes, int n_in,
                              void* d_out, int out_size)
{
    const float* x     = (const float*)d_in[0];
    const int*   mask  = (const int*)d_in[1];
    const float* w_qkv = (const float*)d_in[2];
    const float* w_out = (const float*)d_in[3];
    const float* b_out = (const float*)d_in[4];

    float* out = (float*)d_out;
    const size_t out_elems  = (size_t)Bn * Nn * Dn;
    const size_t attn_elems = (size_t)Bn * Hn * Nn * Nn;
    float* attn = ((size_t)out_size >= out_elems + attn_elems) ? out + out_elems : nullptr;

    __nv_bfloat16 *xhi, *xlo, *wqkvThi, *wqkvTlo, *woutThi, *woutTlo, *hhi, *hlo;
    __nv_bfloat16 *qhi, *qlo, *khi, *klo, *vhi, *vlo;
    float* rowinv;
    cudaGetSymbolAddress((void**)&xhi, g_xhi);
    cudaGetSymbolAddress((void**)&xlo, g_xlo);
    cudaGetSymbolAddress((void**)&wqkvThi, g_wqkvThi);
    cudaGetSymbolAddress((void**)&wqkvTlo, g_wqkvTlo);
    cudaGetSymbolAddress((void**)&woutThi, g_woutThi);
    cudaGetSymbolAddress((void**)&woutTlo, g_woutTlo);
    cudaGetSymbolAddress((void**)&hhi, g_hhi);
    cudaGetSymbolAddress((void**)&hlo, g_hlo);
    cudaGetSymbolAddress((void**)&qhi, g_qhi);
    cudaGetSymbolAddress((void**)&qlo, g_qlo);
    cudaGetSymbolAddress((void**)&khi, g_khi);
    cudaGetSymbolAddress((void**)&klo, g_klo);
    cudaGetSymbolAddress((void**)&vhi, g_vhi);
    cudaGetSymbolAddress((void**)&vlo, g_vlo);
    cudaGetSymbolAddress((void**)&rowinv, g_rowinv);

    cudaFuncSetAttribute(gemm_qkv, cudaFuncAttributeMaxDynamicSharedMemorySize, SMEM_GEMM);
    cudaFuncSetAttribute(gemm_out, cudaFuncAttributeMaxDynamicSharedMemorySize, SMEM_GEMM);
    cudaFuncSetAttribute(attn_flash, cudaFuncAttributeMaxDynamicSharedMemorySize, SMEM_ATTN);

    const int n4x = (Bn * Nn * Dn) / 4;

    // 1) splits
    split_kernel<<<(n4x + 255) / 256, 256>>>((const float4*)x,
                                             (__nv_bfloat162*)xhi, (__nv_bfloat162*)xlo, n4x);
    splitT_kernel<<<dim3(D3 / 32, Dn / 32), dim3(32, 8)>>>(w_qkv, wqkvThi, wqkvTlo, Dn, D3);
    splitT_kernel<<<dim3(Dn / 32, Dn / 32), dim3(32, 8)>>>(w_out, woutThi, woutTlo, Dn, Dn);

    // 2) QKV projection, fused split into per-head q/k/v hi/lo
    gemm_qkv<<<dim3(D3 / 128, (Bn * Nn) / 128), 256, SMEM_GEMM>>>(
        xhi, xlo, wqkvThi, wqkvTlo, qhi, qlo, khi, klo, vhi, vlo);

    // 3) flash attention (writes unnormalized attn + rowinv + hhi/hlo)
    attn_flash<<<dim3(Nn / 64, Bn * Hn), 256, SMEM_ATTN>>>(
        qhi, qlo, khi, klo, vhi, vlo, mask, attn, hhi, hlo);

    // 4) output projection (default stream) CONCURRENT with attn normalize
    //    (forked stream) — both depend only on attn_flash. Graph capture
    //    turns the event record/wait pairs into dependency edges.
    if (attn) {
        cudaStream_t s2;
        cudaEvent_t evFork, evJoin;
        cudaStreamCreateWithFlags(&s2, cudaStreamNonBlocking);
        cudaEventCreateWithFlags(&evFork, cudaEventDisableTiming);
        cudaEventCreateWithFlags(&evJoin, cudaEventDisableTiming);

        cudaEventRecord(evFork, 0);              // after attn_flash
        cudaStreamWaitEvent(s2, evFork, 0);      // fork

        norm_attn<<<(int)(attn_elems / 4 / 256), 256, 0, s2>>>((float4*)attn, rowinv);

        gemm_out<<<dim3(Dn / 128, (Bn * Nn) / 128), 256, SMEM_GEMM>>>(
            hhi, hlo, woutThi, woutTlo, out, b_out);

        cudaEventRecord(evJoin, s2);             // join
        cudaStreamWaitEvent(0, evJoin, 0);

        cudaEventDestroy(evFork);
        cudaEventDestroy(evJoin);
        cudaStreamDestroy(s2);
    } else {
        gemm_out<<<dim3(Dn / 128, (Bn * Nn) / 128), 256, SMEM_GEMM>>>(
            hhi, hlo, woutThi, woutTlo, out, b_out);
    }
}

// round 15
// speedup vs baseline: 1.2190x; 1.0863x over previous
#include <cuda_runtime.h>
#include <cuda_bf16.h>
#include <cstdint>

// Problem constants
#define Bn 8
#define Nn 1024
#define Dn 1024
#define Hn 16
#define DHn 64
#define D3 3072
#define Kdim 1024

// ---------------------------------------------------------------------------
// Device scratch (allocation-free)
// ---------------------------------------------------------------------------
__device__ __nv_bfloat16 g_xhi[(size_t)Bn * Nn * Dn];
__device__ __nv_bfloat16 g_xlo[(size_t)Bn * Nn * Dn];
__device__ __nv_bfloat16 g_wqkvThi[(size_t)D3 * Dn];
__device__ __nv_bfloat16 g_wqkvTlo[(size_t)D3 * Dn];
__device__ __nv_bfloat16 g_woutThi[(size_t)Dn * Dn];
__device__ __nv_bfloat16 g_woutTlo[(size_t)Dn * Dn];
__device__ __nv_bfloat16 g_hhi[(size_t)Bn * Nn * Dn];
__device__ __nv_bfloat16 g_hlo[(size_t)Bn * Nn * Dn];
#define HEADELEMS ((size_t)Bn * Hn * Nn * DHn)
__device__ __nv_bfloat16 g_qhi[HEADELEMS];
__device__ __nv_bfloat16 g_qlo[HEADELEMS];
__device__ __nv_bfloat16 g_khi[HEADELEMS];
__device__ __nv_bfloat16 g_klo[HEADELEMS];
__device__ __nv_bfloat16 g_vhi[HEADELEMS];
__device__ __nv_bfloat16 g_vlo[HEADELEMS];

// ---------------------------------------------------------------------------
// PTX helpers (baseline sm_80+ features only)
// ---------------------------------------------------------------------------
__device__ __forceinline__ uint32_t smem_u32(const void* p) {
    uint32_t a;
    asm("{ .reg .u64 t; cvta.to.shared.u64 t, %1; cvt.u32.u64 %0, t; }"
        : "=r"(a) : "l"(p));
    return a;
}

#define CP_ASYNC16(dst, gsrc) \
    asm volatile("cp.async.cg.shared.global [%0], [%1], 16;" :: "r"(dst), "l"(gsrc))
#define CP_COMMIT() asm volatile("cp.async.commit_group;" ::: "memory")
#define CP_WAIT2()  asm volatile("cp.async.wait_group 2;" ::: "memory")
#define CP_WAIT1()  asm volatile("cp.async.wait_group 1;" ::: "memory")
#define CP_WAIT0()  asm volatile("cp.async.wait_group 0;" ::: "memory")

#define LDSM_X4(r0, r1, r2, r3, addr) \
    asm volatile("ldmatrix.sync.aligned.m8n8.x4.shared.b16 {%0,%1,%2,%3}, [%4];" \
                 : "=r"(r0), "=r"(r1), "=r"(r2), "=r"(r3) : "r"(addr))

#define LDSM_X4_T(r0, r1, r2, r3, addr) \
    asm volatile("ldmatrix.sync.aligned.m8n8.x4.trans.shared.b16 {%0,%1,%2,%3}, [%4];" \
                 : "=r"(r0), "=r"(r1), "=r"(r2), "=r"(r3) : "r"(addr))

#define MMA16816(d, a, b) \
    asm volatile("mma.sync.aligned.m16n8k16.row.col.f32.bf16.bf16.f32 " \
                 "{%0,%1,%2,%3}, {%4,%5,%6,%7}, {%8,%9}, {%0,%1,%2,%3};" \
                 : "+f"((d)[0]), "+f"((d)[1]), "+f"((d)[2]), "+f"((d)[3]) \
                 : "r"((a)[0]), "r"((a)[1]), "r"((a)[2]), "r"((a)[3]), \
                   "r"((b)[0]), "r"((b)[1]))

__device__ __forceinline__ uint32_t pack_split(float2 p, uint32_t& lo) {
    __nv_bfloat16 hx = __float2bfloat16(p.x), hy = __float2bfloat16(p.y);
    __nv_bfloat16 lx = __float2bfloat16(p.x - __bfloat162float(hx));
    __nv_bfloat16 ly = __float2bfloat16(p.y - __bfloat162float(hy));
    __nv_bfloat162 hv = __halves2bfloat162(hx, hy);
    __nv_bfloat162 lv = __halves2bfloat162(lx, ly);
    lo = *(uint32_t*)&lv;
    return *(uint32_t*)&hv;
}

// swizzled address in a 64B-row tile (gemm): chunk c ^ ((row>>1)&3)
#define SWADDR(base, row, c) \
    ((base) + (uint32_t)(row) * 64u + ((uint32_t)((c) ^ (((row) >> 1) & 3)) << 4))

// ---------------------------------------------------------------------------
// Split kernels
// ---------------------------------------------------------------------------
__global__ __launch_bounds__(256) void split_kernel(
    const float4* __restrict__ in, __nv_bfloat162* __restrict__ hi,
    __nv_bfloat162* __restrict__ lo, int n4)
{
    int i = blockIdx.x * 256 + threadIdx.x;
    if (i >= n4) return;
    float4 v = in[i];
    __nv_bfloat16 h0 = __float2bfloat16(v.x), h1 = __float2bfloat16(v.y);
    __nv_bfloat16 h2 = __float2bfloat16(v.z), h3 = __float2bfloat16(v.w);
    __nv_bfloat16 l0 = __float2bfloat16(v.x - __bfloat162float(h0));
    __nv_bfloat16 l1 = __float2bfloat16(v.y - __bfloat162float(h1));
    __nv_bfloat16 l2 = __float2bfloat16(v.z - __bfloat162float(h2));
    __nv_bfloat16 l3 = __float2bfloat16(v.w - __bfloat162float(h3));
    hi[2 * i]     = __halves2bfloat162(h0, h1);
    hi[2 * i + 1] = __halves2bfloat162(h2, h3);
    lo[2 * i]     = __halves2bfloat162(l0, l1);
    lo[2 * i + 1] = __halves2bfloat162(l2, l3);
}

__global__ __launch_bounds__(256) void splitT_kernel(
    const float* __restrict__ in, __nv_bfloat16* __restrict__ hiT,
    __nv_bfloat16* __restrict__ loT, int R, int C)
{
    __shared__ float t[32][33];
    int bx = blockIdx.x * 32;
    int by = blockIdx.y * 32;
    int x = threadIdx.x, y = threadIdx.y;  // 32 x 8
    #pragma unroll
    for (int i = y; i < 32; i += 8)
        t[i][x] = in[(size_t)(by + i) * C + bx + x];
    __syncthreads();
    #pragma unroll
    for (int i = y; i < 32; i += 8) {
        float v = t[x][i];
        __nv_bfloat16 h = __float2bfloat16(v);
        size_t o = (size_t)(bx + i) * R + by + x;
        hiT[o] = h;
        loT[o] = __float2bfloat16(v - __bfloat162float(h));
    }
}

// ---------------------------------------------------------------------------
// bf16-split GEMM, mode 1 (QKV projection + per-head split).
// ---------------------------------------------------------------------------
#define TILEB (128 * 64)
#define STAGEB (4 * TILEB)
#define NSTAGE 3
#define SMEM_GEMM (NSTAGE * STAGEB)    // 98304
#define NCHUNK (Kdim / 32)

__global__ __launch_bounds__(256, 2) void gemm_qkv(
    const __nv_bfloat16* __restrict__ Ahi, const __nv_bfloat16* __restrict__ Alo,
    const __nv_bfloat16* __restrict__ BThi, const __nv_bfloat16* __restrict__ BTlo,
    __nv_bfloat16* __restrict__ qhi, __nv_bfloat16* __restrict__ qlo,
    __nv_bfloat16* __restrict__ khi, __nv_bfloat16* __restrict__ klo,
    __nv_bfloat16* __restrict__ vhi, __nv_bfloat16* __restrict__ vlo)
{
    extern __shared__ char smem[];
    const uint32_t sb = smem_u32(smem);
    const int tid = threadIdx.x, wid = tid >> 5, lane = tid & 31;
    const int wm = wid >> 1;
    const int wn = wid & 1;
    const int ctaM = blockIdx.y * 128, ctaN = blockIdx.x * 128;

    const __nv_bfloat16* gsrc[4] = {
        Ahi + (size_t)ctaM * Kdim, Alo + (size_t)ctaM * Kdim,
        BThi + (size_t)ctaN * Kdim, BTlo + (size_t)ctaN * Kdim};

    auto load_chunk = [&](int s, int k0) {
        uint32_t base = sb + s * STAGEB;
        #pragma unroll
        for (int t = 0; t < 4; t++) {
            uint32_t tb = base + t * TILEB;
            const __nv_bfloat16* g = gsrc[t] + k0;
            #pragma unroll
            for (int i = tid; i < 512; i += 256) {
                int r = i >> 2, c = i & 3;
                uint32_t dst = SWADDR(tb, r, c);
                size_t gs = __cvta_generic_to_global(g + (size_t)r * Kdim + c * 8);
                CP_ASYNC16(dst, gs);
            }
        }
        CP_COMMIT();
    };

    float acc[2][8][4];
    #pragma unroll
    for (int i = 0; i < 2; i++)
        #pragma unroll
        for (int j = 0; j < 8; j++)
            #pragma unroll
            for (int k = 0; k < 4; k++) acc[i][j][k] = 0.f;

    load_chunk(0, 0);
    load_chunk(1, 32);

    const int q = lane >> 3, l8 = lane & 7;
    const int arow = wm * 32 + (q & 1) * 8 + l8;
    const int brow = wn * 64 + (q >> 1) * 8 + l8;
    const int acsel = q >> 1;
    const int bcsel = q & 1;

    for (int c = 0; c < NCHUNK; c++) {
        int s = c % NSTAGE;
        if (c == NCHUNK - 1) CP_WAIT0(); else CP_WAIT1();
        __syncthreads();

        uint32_t base = sb + s * STAGEB;
        uint32_t tAh = base, tAl = base + TILEB;
        uint32_t tBh = base + 2 * TILEB, tBl = base + 3 * TILEB;

        #pragma unroll
        for (int kk = 0; kk < 2; kk++) {
            int ca = kk * 2 + acsel;
            int cb = kk * 2 + bcsel;
            uint32_t ah[2][4], al[2][4];
            #pragma unroll
            for (int mf = 0; mf < 2; mf++) {
                int row = arow + mf * 16;
                LDSM_X4(ah[mf][0], ah[mf][1], ah[mf][2], ah[mf][3], SWADDR(tAh, row, ca));
                LDSM_X4(al[mf][0], al[mf][1], al[mf][2], al[mf][3], SWADDR(tAl, row, ca));
            }
            #pragma unroll
            for (int nf2 = 0; nf2 < 4; nf2++) {
                uint32_t bh0[2], bh1[2], bl0[2], bl1[2];
                int row = brow + nf2 * 16;
                LDSM_X4(bh0[0], bh0[1], bh1[0], bh1[1], SWADDR(tBh, row, cb));
                LDSM_X4(bl0[0], bl0[1], bl1[0], bl1[1], SWADDR(tBl, row, cb));
                int n0 = 2 * nf2, n1 = 2 * nf2 + 1;
                MMA16816(acc[0][n0], ah[0], bh0);
                MMA16816(acc[0][n1], ah[0], bh1);
                MMA16816(acc[1][n0], ah[1], bh0);
                MMA16816(acc[1][n1], ah[1], bh1);
                MMA16816(acc[0][n0], ah[0], bl0);
                MMA16816(acc[0][n1], ah[0], bl1);
                MMA16816(acc[1][n0], ah[1], bl0);
                MMA16816(acc[1][n1], ah[1], bl1);
                MMA16816(acc[0][n0], al[0], bh0);
                MMA16816(acc[0][n1], al[0], bh1);
                MMA16816(acc[1][n0], al[1], bh0);
                MMA16816(acc[1][n1], al[1], bh1);
            }
        }
        if (c + NSTAGE - 1 < NCHUNK) load_chunk((c + 2) % NSTAGE, (c + 2) * 32);
    }

    #pragma unroll
    for (int mf = 0; mf < 2; mf++) {
        int row = ctaM + wm * 32 + mf * 16 + (lane >> 2);
        int b = row >> 10, n = row & 1023;
        #pragma unroll
        for (int nf = 0; nf < 8; nf++) {
            int col = ctaN + wn * 64 + nf * 8 + (lane & 3) * 2;
            int s = col >> 10, hh = (col >> 6) & 15, dh = col & 63;
            float sc = (s == 0) ? 0.125f : 1.0f;
            __nv_bfloat16* hiP = (s == 0) ? qhi : (s == 1) ? khi : vhi;
            __nv_bfloat16* loP = (s == 0) ? qlo : (s == 1) ? klo : vlo;
            size_t o0 = (((size_t)(b * 16 + hh)) * 1024 + n) * 64 + dh;
            size_t o1 = o0 + 8 * 64;
            uint32_t lo;
            uint32_t hi = pack_split(
                make_float2(acc[mf][nf][0] * sc, acc[mf][nf][1] * sc), lo);
            *(uint32_t*)&hiP[o0] = hi;
            *(uint32_t*)&loP[o0] = lo;
            hi = pack_split(
                make_float2(acc[mf][nf][2] * sc, acc[mf][nf][3] * sc), lo);
            *(uint32_t*)&hiP[o1] = hi;
            *(uint32_t*)&loP[o1] = lo;
        }
    }
}

// ---------------------------------------------------------------------------
// bf16-split GEMM, mode 0 (output projection + bias) — clean.
// ---------------------------------------------------------------------------
__global__ __launch_bounds__(256, 2) void gemm_out(
    const __nv_bfloat16* __restrict__ Ahi, const __nv_bfloat16* __restrict__ Alo,
    const __nv_bfloat16* __restrict__ BThi, const __nv_bfloat16* __restrict__ BTlo,
    float* __restrict__ C, const float* __restrict__ bias)
{
    extern __shared__ char smem[];
    const uint32_t sb = smem_u32(smem);
    const int tid = threadIdx.x, wid = tid >> 5, lane = tid & 31;
    const int wm = wid >> 1;
    const int wn = wid & 1;
    const int ctaM = blockIdx.y * 128, ctaN = blockIdx.x * 128;

    const __nv_bfloat16* gsrc[4] = {
        Ahi + (size_t)ctaM * Kdim, Alo + (size_t)ctaM * Kdim,
        BThi + (size_t)ctaN * Kdim, BTlo + (size_t)ctaN * Kdim};

    auto load_chunk = [&](int s, int k0) {
        uint32_t base = sb + s * STAGEB;
        #pragma unroll
        for (int t = 0; t < 4; t++) {
            uint32_t tb = base + t * TILEB;
            const __nv_bfloat16* g = gsrc[t] + k0;
            #pragma unroll
            for (int i = tid; i < 512; i += 256) {
                int r = i >> 2, c = i & 3;
                uint32_t dst = SWADDR(tb, r, c);
                size_t gs = __cvta_generic_to_global(g + (size_t)r * Kdim + c * 8);
                CP_ASYNC16(dst, gs);
            }
        }
        CP_COMMIT();
    };

    float acc[2][8][4];
    #pragma unroll
    for (int i = 0; i < 2; i++)
        #pragma unroll
        for (int j = 0; j < 8; j++)
            #pragma unroll
            for (int k = 0; k < 4; k++) acc[i][j][k] = 0.f;

    load_chunk(0, 0);
    load_chunk(1, 32);

    const int q = lane >> 3, l8 = lane & 7;
    const int arow = wm * 32 + (q & 1) * 8 + l8;
    const int brow = wn * 64 + (q >> 1) * 8 + l8;
    const int acsel = q >> 1;
    const int bcsel = q & 1;

    for (int c = 0; c < NCHUNK; c++) {
        int s = c % NSTAGE;
        if (c == NCHUNK - 1) CP_WAIT0(); else CP_WAIT1();
        __syncthreads();

        uint32_t base = sb + s * STAGEB;
        uint32_t tAh = base, tAl = base + TILEB;
        uint32_t tBh = base + 2 * TILEB, tBl = base + 3 * TILEB;

        #pragma unroll
        for (int kk = 0; kk < 2; kk++) {
            int ca = kk * 2 + acsel;
            int cb = kk * 2 + bcsel;
            uint32_t ah[2][4], al[2][4];
            #pragma unroll
            for (int mf = 0; mf < 2; mf++) {
                int row = arow + mf * 16;
                LDSM_X4(ah[mf][0], ah[mf][1], ah[mf][2], ah[mf][3], SWADDR(tAh, row, ca));
                LDSM_X4(al[mf][0], al[mf][1], al[mf][2], al[mf][3], SWADDR(tAl, row, ca));
            }
            #pragma unroll
            for (int nf2 = 0; nf2 < 4; nf2++) {
                uint32_t bh0[2], bh1[2], bl0[2], bl1[2];
                int row = brow + nf2 * 16;
                LDSM_X4(bh0[0], bh0[1], bh1[0], bh1[1], SWADDR(tBh, row, cb));
                LDSM_X4(bl0[0], bl0[1], bl1[0], bl1[1], SWADDR(tBl, row, cb));
                int n0 = 2 * nf2, n1 = 2 * nf2 + 1;
                MMA16816(acc[0][n0], ah[0], bh0);
                MMA16816(acc[0][n1], ah[0], bh1);
                MMA16816(acc[1][n0], ah[1], bh0);
                MMA16816(acc[1][n1], ah[1], bh1);
                MMA16816(acc[0][n0], ah[0], bl0);
                MMA16816(acc[0][n1], ah[0], bl1);
                MMA16816(acc[1][n0], ah[1], bl0);
                MMA16816(acc[1][n1], ah[1], bl1);
                MMA16816(acc[0][n0], al[0], bh0);
                MMA16816(acc[0][n1], al[0], bh1);
                MMA16816(acc[1][n0], al[1], bh0);
                MMA16816(acc[1][n1], al[1], bh1);
            }
        }
        if (c + NSTAGE - 1 < NCHUNK) load_chunk((c + 2) % NSTAGE, (c + 2) * 32);
    }

    #pragma unroll
    for (int mf = 0; mf < 2; mf++) {
        int row = ctaM + wm * 32 + mf * 16 + (lane >> 2);
        #pragma unroll
        for (int nf = 0; nf < 8; nf++) {
            int col = ctaN + wn * 64 + nf * 8 + (lane & 3) * 2;
            float bx = bias[col], by = bias[col + 1];
            float2 v0 = {acc[mf][nf][0] + bx, acc[mf][nf][1] + by};
            float2 v1 = {acc[mf][nf][2] + bx, acc[mf][nf][3] + by};
            *(float2*)&C[(size_t)row * Dn + col] = v0;
            *(float2*)&C[(size_t)(row + 8) * Dn + col] = v1;
        }
    }
}

// ---------------------------------------------------------------------------
// Flash-style attention with IN-KERNEL attn rescale: the CTA re-reads its own
// just-written 256 KB attn slice (L2-resident: 128 CTAs x 256 KB = 32 MB) and
// scales by 1/rowsum — unnormalized dirty lines are overwritten in L2 before
// eviction, cutting attn DRAM traffic to the single final write.
// ---------------------------------------------------------------------------
#define KSTRIDE 144
#define APLANE (64 * KSTRIDE)
#define OFF_Q   0
#define OFF_STG (2 * APLANE)
#define ASTGB  (4 * APLANE)
#define OFF_MASK (OFF_STG + 2 * ASTGB)
#define OFF_PART (OFF_MASK + 4096)
#define OFF_INV  (OFF_PART + 512)
#define SMEM_ATTN (OFF_INV + 256)          // 97024

__global__ __launch_bounds__(256, 2) void attn_flash(
    const __nv_bfloat16* __restrict__ qhi, const __nv_bfloat16* __restrict__ qlo,
    const __nv_bfloat16* __restrict__ khi, const __nv_bfloat16* __restrict__ klo,
    const __nv_bfloat16* __restrict__ vhi, const __nv_bfloat16* __restrict__ vlo,
    const int* __restrict__ mask, float* __restrict__ attn,
    __nv_bfloat16* __restrict__ hhi, __nv_bfloat16* __restrict__ hlo)
{
    extern __shared__ char smem[];
    const uint32_t sb = smem_u32(smem);
    const int tid = threadIdx.x, wid = tid >> 5, lane = tid & 31;
    const int q8 = lane >> 3, l8 = lane & 7;
    const int wm = wid & 3, wn = wid >> 2;
    const int bh = blockIdx.y, b = bh >> 4, h = bh & 15;
    const int q0 = blockIdx.x * 64;
    const size_t head_base = (size_t)bh * Nn * DHn;

    auto load_tile = [&](int tile, int s) {
        uint32_t stg = sb + OFF_STG + s * ASTGB;
        const __nv_bfloat16* planes[4] = {khi, klo, vhi, vlo};
        #pragma unroll
        for (int i = tid; i < 2048; i += 256) {
            int pl = i >> 9, r = (i >> 3) & 63, c = i & 7;
            const __nv_bfloat16* src = planes[pl] + head_base +
                                       (size_t)(tile * 64 + r) * 64 + c * 8;
            uint32_t dst = stg + pl * APLANE + r * KSTRIDE + c * 16;
            CP_ASYNC16(dst, __cvta_generic_to_global(src));
        }
        CP_COMMIT();
    };

    #pragma unroll
    for (int i = tid; i < 1024; i += 256) {
        int pl = i >> 9, r = (i >> 3) & 63, c = i & 7;
        const __nv_bfloat16* src = (pl ? qlo : qhi) + head_base +
                                   (size_t)(q0 + r) * 64 + c * 8;
        uint32_t dst = sb + OFF_Q + pl * APLANE + r * KSTRIDE + c * 16;
        CP_ASYNC16(dst, __cvta_generic_to_global(src));
    }
    CP_COMMIT();
    load_tile(0, 0);
    load_tile(1, 1);

    {
        int4 mv = ((const int4*)(mask + b * Nn))[tid];
        float4 f = make_float4(mv.x ? 1.f : 0.f, mv.y ? 1.f : 0.f,
                               mv.z ? 1.f : 0.f, mv.w ? 1.f : 0.f);
        ((float4*)(smem + OFF_MASK))[tid] = f;
    }

    uint32_t qfh[4][4], qfl[4][4];
    CP_WAIT2();
    __syncthreads();
    {
        uint32_t qhb = sb + OFF_Q, qlb = sb + OFF_Q + APLANE;
        #pragma unroll
        for (int kk = 0; kk < 4; kk++) {
            uint32_t ao = (uint32_t)((wm * 16 + (q8 & 1) * 8 + l8) * KSTRIDE +
                                     (q8 >> 1) * 16 + kk * 32);
            LDSM_X4(qfh[kk][0], qfh[kk][1], qfh[kk][2], qfh[kk][3], qhb + ao);
            LDSM_X4(qfl[kk][0], qfl[kk][1], qfl[kk][2], qfl[kk][3], qlb + ao);
        }
    }

    const float* mskf = (const float*)(smem + OFF_MASK);
    const int r0 = wm * 16 + (lane >> 2);
    float sum0 = 0.f, sum1 = 0.f;

    float oacc[8][4];
    #pragma unroll
    for (int i = 0; i < 8; i++)
        #pragma unroll
        for (int j = 0; j < 4; j++) oacc[i][j] = 0.f;

    float* attn_row = attn ? attn + ((size_t)bh * Nn + q0 + r0) * Nn : nullptr;

    for (int kt = 0; kt < 16; kt++) {
        if (kt == 15) CP_WAIT0(); else CP_WAIT1();
        __syncthreads();
        uint32_t stg = sb + OFF_STG + (kt & 1) * ASTGB;
        uint32_t khb = stg, klb = stg + APLANE;
        uint32_t vhb = stg + 2 * APLANE, vlb = stg + 3 * APLANE;

        float acc[4][4];
        #pragma unroll
        for (int i = 0; i < 4; i++)
            #pragma unroll
            for (int j = 0; j < 4; j++) acc[i][j] = 0.f;

        #pragma unroll
        for (int kk = 0; kk < 4; kk++) {
            uint32_t bfh[4][2], bfl[4][2];
            #pragma unroll
            for (int pr = 0; pr < 2; pr++) {
                uint32_t bo = (uint32_t)((wn * 32 + pr * 16 + (q8 >> 1) * 8 + l8) * KSTRIDE +
                                         (q8 & 1) * 16 + kk * 32);
                LDSM_X4(bfh[2*pr][0], bfh[2*pr][1], bfh[2*pr+1][0], bfh[2*pr+1][1], khb + bo);
                LDSM_X4(bfl[2*pr][0], bfl[2*pr][1], bfl[2*pr+1][0], bfl[2*pr+1][1], klb + bo);
            }
            #pragma unroll
            for (int nf = 0; nf < 4; nf++) MMA16816(acc[nf], qfh[kk], bfh[nf]);
            #pragma unroll
            for (int nf = 0; nf < 4; nf++) MMA16816(acc[nf], qfh[kk], bfl[nf]);
            #pragma unroll
            for (int nf = 0; nf < 4; nf++) MMA16816(acc[nf], qfl[kk], bfh[nf]);
        }

        #pragma unroll
        for (int nf = 0; nf < 4; nf++) {
            int col = kt * 64 + wn * 32 + nf * 8 + (lane & 3) * 2;
            float2 mv = *(const float2*)&mskf[col];
            acc[nf][0] = __expf(acc[nf][0]) * mv.x;
            acc[nf][1] = __expf(acc[nf][1]) * mv.y;
            acc[nf][2] = __expf(acc[nf][2]) * mv.x;
            acc[nf][3] = __expf(acc[nf][3]) * mv.y;
            sum0 += acc[nf][0] + acc[nf][1];
            sum1 += acc[nf][2] + acc[nf][3];
            if (attn_row) {
                *(float2*)&attn_row[col] = make_float2(acc[nf][0], acc[nf][1]);
                *(float2*)&attn_row[8 * Nn + col] = make_float2(acc[nf][2], acc[nf][3]);
            }
        }

        uint32_t ah[2][4], al[2][4];
        #pragma unroll
        for (int f = 0; f < 2; f++) {
            ah[f][0] = pack_split(make_float2(acc[2*f][0],   acc[2*f][1]),   al[f][0]);
            ah[f][1] = pack_split(make_float2(acc[2*f][2],   acc[2*f][3]),   al[f][1]);
            ah[f][2] = pack_split(make_float2(acc[2*f+1][0], acc[2*f+1][1]), al[f][2]);
            ah[f][3] = pack_split(make_float2(acc[2*f+1][2], acc[2*f+1][3]), al[f][3]);
        }

        #pragma unroll
        for (int f = 0; f < 2; f++) {
            #pragma unroll
            for (int dq = 0; dq < 4; dq++) {
                uint32_t vo = (uint32_t)((wn * 32 + f * 16 + (q8 & 1) * 8 + l8) * KSTRIDE +
                                         dq * 32 + (q8 >> 1) * 16);
                uint32_t vh0[2], vh1[2], vl0[2], vl1[2];
                LDSM_X4_T(vh0[0], vh0[1], vh1[0], vh1[1], vhb + vo);
                LDSM_X4_T(vl0[0], vl0[1], vl1[0], vl1[1], vlb + vo);
                MMA16816(oacc[2*dq],     ah[f], vh0);
                MMA16816(oacc[2*dq + 1], ah[f], vh1);
                MMA16816(oacc[2*dq],     ah[f], vl0);
                MMA16816(oacc[2*dq + 1], ah[f], vl1);
                MMA16816(oacc[2*dq],     al[f], vh0);
                MMA16816(oacc[2*dq + 1], al[f], vh1);
            }
        }

        __syncthreads();
        if (kt + 2 < 16) load_tile(kt + 2, kt & 1);
    }

    sum0 += __shfl_xor_sync(0xffffffffu, sum0, 1);
    sum0 += __shfl_xor_sync(0xffffffffu, sum0, 2);
    sum1 += __shfl_xor_sync(0xffffffffu, sum1, 1);
    sum1 += __shfl_xor_sync(0xffffffffu, sum1, 2);
    {
        float* part = (float*)(smem + OFF_PART);
        if ((lane & 3) == 0) {
            part[wn * 64 + r0]     = sum0;
            part[wn * 64 + r0 + 8] = sum1;
        }
    }
    {
        uint32_t slot = sb + OFF_STG + wid * 4096;
        #pragma unroll
        for (int nt = 0; nt < 8; nt++) {
            uint32_t a0 = slot + (uint32_t)(lane >> 2) * 256 + (nt * 8 + (lane & 3) * 2) * 4;
            *(float2*)(smem + (a0 - sb)) = make_float2(oacc[nt][0], oacc[nt][1]);
            *(float2*)(smem + (a0 - sb) + 8 * 256) = make_float2(oacc[nt][2], oacc[nt][3]);
        }
    }
    __syncthreads();
    {
        const float* part = (const float*)(smem + OFF_PART);
        float* invs = (float*)(smem + OFF_INV);
        if (tid < 64)
            invs[tid] = 1.f / (part[tid] + part[64 + tid]);
    }
    __syncthreads();

    // ---- O reduce across wn halves, scale, write heads bf16 hi/lo ----
    {
        const float* invs = (const float*)(smem + OFF_INV);
        int r = wid * 8 + (lane >> 2);
        int c0 = (lane & 3) * 16;
        int strip = r >> 4, rl = r & 15;
        const float* s0 = (const float*)(smem + OFF_STG + strip * 4096) + rl * 64 + c0;
        const float* s1 = (const float*)(smem + OFF_STG + (strip + 4) * 4096) + rl * 64 + c0;
        float inv = invs[r];
        size_t dbase = ((size_t)(b * Nn) + q0 + r) * Dn + h * 64 + c0;
        #pragma unroll
        for (int c = 0; c < 16; c += 2) {
            float v0 = (s0[c]     + s1[c])     * inv;
            float v1 = (s0[c + 1] + s1[c + 1]) * inv;
            uint32_t lo;
            uint32_t hi = pack_split(make_float2(v0, v1), lo);
            *(uint32_t*)&hhi[dbase + c] = hi;
            *(uint32_t*)&hlo[dbase + c] = lo;
        }
    }

    // ---- in-kernel attn rescale: this CTA's 64 rows (L2-hot) ----
    if (attn) {
        const float* invs = (const float*)(smem + OFF_INV);
        float4* attn4 = (float4*)(attn + ((size_t)bh * Nn + q0) * Nn);
        #pragma unroll 4
        for (int i = tid; i < 64 * 256; i += 256) {
            int r = i >> 8;                  // warp-uniform per iteration
            float inv = invs[r];
            float4 v = attn4[i];
            v.x *= inv; v.y *= inv; v.z *= inv; v.w *= inv;
            attn4[i] = v;
        }
    }
}

// ---------------------------------------------------------------------------

extern "C" void kernel_launch(void* const* d_in, const int* in_sizes, int n_in,
                              void* d_out, int out_size)
{
    const float* x     = (const float*)d_in[0];
    const int*   mask  = (const int*)d_in[1];
    const float* w_qkv = (const float*)d_in[2];
    const float* w_out = (const float*)d_in[3];
    const float* b_out = (const float*)d_in[4];

    float* out = (float*)d_out;
    const size_t out_elems  = (size_t)Bn * Nn * Dn;
    const size_t attn_elems = (size_t)Bn * Hn * Nn * Nn;
    float* attn = ((size_t)out_size >= out_elems + attn_elems) ? out + out_elems : nullptr;

    __nv_bfloat16 *xhi, *xlo, *wqkvThi, *wqkvTlo, *woutThi, *woutTlo, *hhi, *hlo;
    __nv_bfloat16 *qhi, *qlo, *khi, *klo, *vhi, *vlo;
    cudaGetSymbolAddress((void**)&xhi, g_xhi);
    cudaGetSymbolAddress((void**)&xlo, g_xlo);
    cudaGetSymbolAddress((void**)&wqkvThi, g_wqkvThi);
    cudaGetSymbolAddress((void**)&wqkvTlo, g_wqkvTlo);
    cudaGetSymbolAddress((void**)&woutThi, g_woutThi);
    cudaGetSymbolAddress((void**)&woutTlo, g_woutTlo);
    cudaGetSymbolAddress((void**)&hhi, g_hhi);
    cudaGetSymbolAddress((void**)&hlo, g_hlo);
    cudaGetSymbolAddress((void**)&qhi, g_qhi);
    cudaGetSymbolAddress((void**)&qlo, g_qlo);
    cudaGetSymbolAddress((void**)&khi, g_khi);
    cudaGetSymbolAddress((void**)&klo, g_klo);
    cudaGetSymbolAddress((void**)&vhi, g_vhi);
    cudaGetSymbolAddress((void**)&vlo, g_vlo);

    cudaFuncSetAttribute(gemm_qkv, cudaFuncAttributeMaxDynamicSharedMemorySize, SMEM_GEMM);
    cudaFuncSetAttribute(gemm_out, cudaFuncAttributeMaxDynamicSharedMemorySize, SMEM_GEMM);
    cudaFuncSetAttribute(attn_flash, cudaFuncAttributeMaxDynamicSharedMemorySize, SMEM_ATTN);

    const int n4x = (Bn * Nn * Dn) / 4;

    // 1) splits
    split_kernel<<<(n4x + 255) / 256, 256>>>((const float4*)x,
                                             (__nv_bfloat162*)xhi, (__nv_bfloat162*)xlo, n4x);
    splitT_kernel<<<dim3(D3 / 32, Dn / 32), dim3(32, 8)>>>(w_qkv, wqkvThi, wqkvTlo, Dn, D3);
    splitT_kernel<<<dim3(Dn / 32, Dn / 32), dim3(32, 8)>>>(w_out, woutThi, woutTlo, Dn, Dn);

    // 2) QKV projection, fused split into per-head q/k/v hi/lo
    gemm_qkv<<<dim3(D3 / 128, (Bn * Nn) / 128), 256, SMEM_GEMM>>>(
        xhi, xlo, wqkvThi, wqkvTlo, qhi, qlo, khi, klo, vhi, vlo);

    // 3) flash attention (writes normalized attn via in-kernel rescale + heads)
    attn_flash<<<dim3(Nn / 64, Bn * Hn), 256, SMEM_ATTN>>>(
        qhi, qlo, khi, klo, vhi, vlo, mask, attn, hhi, hlo);

    // 4) output projection with bias
    gemm_out<<<dim3(Dn / 128, (Bn * Nn) / 128), 256, SMEM_GEMM>>>(
        hhi, hlo, woutThi, woutTlo, out, b_out);
}

// round 16
// speedup vs baseline: 1.2225x; 1.0029x over previous
#include <cuda_runtime.h>
#include <cuda_bf16.h>
#include <cstdint>

// Problem constants
#define Bn 8
#define Nn 1024
#define Dn 1024
#define Hn 16
#define DHn 64
#define D3 3072
#define Kdim 1024

// ---------------------------------------------------------------------------
// Device scratch (allocation-free)
// ---------------------------------------------------------------------------
__device__ __nv_bfloat16 g_xhi[(size_t)Bn * Nn * Dn];
__device__ __nv_bfloat16 g_xlo[(size_t)Bn * Nn * Dn];
__device__ __nv_bfloat16 g_wqkvThi[(size_t)D3 * Dn];
__device__ __nv_bfloat16 g_wqkvTlo[(size_t)D3 * Dn];
__device__ __nv_bfloat16 g_woutThi[(size_t)Dn * Dn];
__device__ __nv_bfloat16 g_woutTlo[(size_t)Dn * Dn];
__device__ __nv_bfloat16 g_hhi[(size_t)Bn * Nn * Dn];
__device__ __nv_bfloat16 g_hlo[(size_t)Bn * Nn * Dn];
#define HEADELEMS ((size_t)Bn * Hn * Nn * DHn)
__device__ __nv_bfloat16 g_qhi[HEADELEMS];
__device__ __nv_bfloat16 g_qlo[HEADELEMS];
__device__ __nv_bfloat16 g_khi[HEADELEMS];
__device__ __nv_bfloat16 g_klo[HEADELEMS];
__device__ __nv_bfloat16 g_vhi[HEADELEMS];
__device__ __nv_bfloat16 g_vlo[HEADELEMS];
// dataflow flags (zeroed by split_kernel each launch)
__device__ int g_flag_qkv[8];     // per batch: 192 gemm_qkv producers
__device__ int g_flag_row[64];    // per 128-token block: 32 attn producers

// ---------------------------------------------------------------------------
// PTX helpers (baseline sm_80+ features only)
// ---------------------------------------------------------------------------
__device__ __forceinline__ uint32_t smem_u32(const void* p) {
    uint32_t a;
    asm("{ .reg .u64 t; cvta.to.shared.u64 t, %1; cvt.u32.u64 %0, t; }"
        : "=r"(a) : "l"(p));
    return a;
}

#define CP_ASYNC16(dst, gsrc) \
    asm volatile("cp.async.cg.shared.global [%0], [%1], 16;" :: "r"(dst), "l"(gsrc))
#define CP_COMMIT() asm volatile("cp.async.commit_group;" ::: "memory")
#define CP_WAIT2()  asm volatile("cp.async.wait_group 2;" ::: "memory")
#define CP_WAIT1()  asm volatile("cp.async.wait_group 1;" ::: "memory")
#define CP_WAIT0()  asm volatile("cp.async.wait_group 0;" ::: "memory")

#define LDSM_X4(r0, r1, r2, r3, addr) \
    asm volatile("ldmatrix.sync.aligned.m8n8.x4.shared.b16 {%0,%1,%2,%3}, [%4];" \
                 : "=r"(r0), "=r"(r1), "=r"(r2), "=r"(r3) : "r"(addr))

#define LDSM_X4_T(r0, r1, r2, r3, addr) \
    asm volatile("ldmatrix.sync.aligned.m8n8.x4.trans.shared.b16 {%0,%1,%2,%3}, [%4];" \
                 : "=r"(r0), "=r"(r1), "=r"(r2), "=r"(r3) : "r"(addr))

#define MMA16816(d, a, b) \
    asm volatile("mma.sync.aligned.m16n8k16.row.col.f32.bf16.bf16.f32 " \
                 "{%0,%1,%2,%3}, {%4,%5,%6,%7}, {%8,%9}, {%0,%1,%2,%3};" \
                 : "+f"((d)[0]), "+f"((d)[1]), "+f"((d)[2]), "+f"((d)[3]) \
                 : "r"((a)[0]), "r"((a)[1]), "r"((a)[2]), "r"((a)[3]), \
                   "r"((b)[0]), "r"((b)[1]))

__device__ __forceinline__ uint32_t pack_split(float2 p, uint32_t& lo) {
    __nv_bfloat16 hx = __float2bfloat16(p.x), hy = __float2bfloat16(p.y);
    __nv_bfloat16 lx = __float2bfloat16(p.x - __bfloat162float(hx));
    __nv_bfloat16 ly = __float2bfloat16(p.y - __bfloat162float(hy));
    __nv_bfloat162 hv = __halves2bfloat162(hx, hy);
    __nv_bfloat162 lv = __halves2bfloat162(lx, ly);
    lo = *(uint32_t*)&lv;
    return *(uint32_t*)&hv;
}

// swizzled address in a 64B-row tile (gemm): chunk c ^ ((row>>1)&3)
#define SWADDR(base, row, c) \
    ((base) + (uint32_t)(row) * 64u + ((uint32_t)((c) ^ (((row) >> 1) & 3)) << 4))

// ---------------------------------------------------------------------------
// Split kernels (split_kernel also zeroes the dataflow flags)
// ---------------------------------------------------------------------------
__global__ __launch_bounds__(256) void split_kernel(
    const float4* __restrict__ in, __nv_bfloat162* __restrict__ hi,
    __nv_bfloat162* __restrict__ lo, int n4)
{
    if (blockIdx.x == 0 && threadIdx.x < 72) {
        if (threadIdx.x < 8) g_flag_qkv[threadIdx.x] = 0;
        else g_flag_row[threadIdx.x - 8] = 0;
    }
    int i = blockIdx.x * 256 + threadIdx.x;
    if (i >= n4) return;
    float4 v = in[i];
    __nv_bfloat16 h0 = __float2bfloat16(v.x), h1 = __float2bfloat16(v.y);
    __nv_bfloat16 h2 = __float2bfloat16(v.z), h3 = __float2bfloat16(v.w);
    __nv_bfloat16 l0 = __float2bfloat16(v.x - __bfloat162float(h0));
    __nv_bfloat16 l1 = __float2bfloat16(v.y - __bfloat162float(h1));
    __nv_bfloat16 l2 = __float2bfloat16(v.z - __bfloat162float(h2));
    __nv_bfloat16 l3 = __float2bfloat16(v.w - __bfloat162float(h3));
    hi[2 * i]     = __halves2bfloat162(h0, h1);
    hi[2 * i + 1] = __halves2bfloat162(h2, h3);
    lo[2 * i]     = __halves2bfloat162(l0, l1);
    lo[2 * i + 1] = __halves2bfloat162(l2, l3);
}

__global__ __launch_bounds__(256) void splitT_kernel(
    const float* __restrict__ in, __nv_bfloat16* __restrict__ hiT,
    __nv_bfloat16* __restrict__ loT, int R, int C)
{
    __shared__ float t[32][33];
    int bx = blockIdx.x * 32;
    int by = blockIdx.y * 32;
    int x = threadIdx.x, y = threadIdx.y;  // 32 x 8
    #pragma unroll
    for (int i = y; i < 32; i += 8)
        t[i][x] = in[(size_t)(by + i) * C + bx + x];
    __syncthreads();
    #pragma unroll
    for (int i = y; i < 32; i += 8) {
        float v = t[x][i];
        __nv_bfloat16 h = __float2bfloat16(v);
        size_t o = (size_t)(bx + i) * R + by + x;
        hiT[o] = h;
        loT[o] = __float2bfloat16(v - __bfloat162float(h));
    }
}

// ---------------------------------------------------------------------------
// Shared tile sizes
// ---------------------------------------------------------------------------
#define TILEB (128 * 64)
#define STAGEB (4 * TILEB)
#define NSTAGE 3
#define SMEM_MEGA (NSTAGE * STAGEB)    // 98304
#define NCHUNK (Kdim / 32)

// ---------------------------------------------------------------------------
// Body: bf16-split GEMM (shared by qkv/out modes)
// mode 1: per-head split write + flag_qkv arrive.  mode 0: C+bias.
// ---------------------------------------------------------------------------
__device__ __forceinline__ void gemm_body(
    int bx, int by, char* smem, int mode,
    const __nv_bfloat16* __restrict__ Ahi, const __nv_bfloat16* __restrict__ Alo,
    const __nv_bfloat16* __restrict__ BThi, const __nv_bfloat16* __restrict__ BTlo,
    float* __restrict__ C, const float* __restrict__ bias,
    __nv_bfloat16* __restrict__ qhi, __nv_bfloat16* __restrict__ qlo,
    __nv_bfloat16* __restrict__ khi, __nv_bfloat16* __restrict__ klo,
    __nv_bfloat16* __restrict__ vhi, __nv_bfloat16* __restrict__ vlo)
{
    const uint32_t sb = smem_u32(smem);
    const int tid = threadIdx.x, wid = tid >> 5, lane = tid & 31;
    const int wm = wid >> 1;
    const int wn = wid & 1;
    const int ctaM = by * 128, ctaN = bx * 128;
    const int Ncols = (mode == 1) ? D3 : Dn;
    (void)Ncols;

    const __nv_bfloat16* gsrc[4] = {
        Ahi + (size_t)ctaM * Kdim, Alo + (size_t)ctaM * Kdim,
        BThi + (size_t)ctaN * Kdim, BTlo + (size_t)ctaN * Kdim};

    auto load_chunk = [&](int s, int k0) {
        uint32_t base = sb + s * STAGEB;
        #pragma unroll
        for (int t = 0; t < 4; t++) {
            uint32_t tb = base + t * TILEB;
            const __nv_bfloat16* g = gsrc[t] + k0;
            #pragma unroll
            for (int i = tid; i < 512; i += 256) {
                int r = i >> 2, c = i & 3;
                uint32_t dst = SWADDR(tb, r, c);
                size_t gs = __cvta_generic_to_global(g + (size_t)r * Kdim + c * 8);
                CP_ASYNC16(dst, gs);
            }
        }
        CP_COMMIT();
    };

    float acc[2][8][4];
    #pragma unroll
    for (int i = 0; i < 2; i++)
        #pragma unroll
        for (int j = 0; j < 8; j++)
            #pragma unroll
            for (int k = 0; k < 4; k++) acc[i][j][k] = 0.f;

    load_chunk(0, 0);
    load_chunk(1, 32);

    const int q = lane >> 3, l8 = lane & 7;
    const int arow = wm * 32 + (q & 1) * 8 + l8;
    const int brow = wn * 64 + (q >> 1) * 8 + l8;
    const int acsel = q >> 1;
    const int bcsel = q & 1;

    for (int c = 0; c < NCHUNK; c++) {
        int s = c % NSTAGE;
        if (c == NCHUNK - 1) CP_WAIT0(); else CP_WAIT1();
        __syncthreads();

        uint32_t base = sb + s * STAGEB;
        uint32_t tAh = base, tAl = base + TILEB;
        uint32_t tBh = base + 2 * TILEB, tBl = base + 3 * TILEB;

        #pragma unroll
        for (int kk = 0; kk < 2; kk++) {
            int ca = kk * 2 + acsel;
            int cb = kk * 2 + bcsel;
            uint32_t ah[2][4], al[2][4];
            #pragma unroll
            for (int mf = 0; mf < 2; mf++) {
                int row = arow + mf * 16;
                LDSM_X4(ah[mf][0], ah[mf][1], ah[mf][2], ah[mf][3], SWADDR(tAh, row, ca));
                LDSM_X4(al[mf][0], al[mf][1], al[mf][2], al[mf][3], SWADDR(tAl, row, ca));
            }
            #pragma unroll
            for (int nf2 = 0; nf2 < 4; nf2++) {
                uint32_t bh0[2], bh1[2], bl0[2], bl1[2];
                int row = brow + nf2 * 16;
                LDSM_X4(bh0[0], bh0[1], bh1[0], bh1[1], SWADDR(tBh, row, cb));
                LDSM_X4(bl0[0], bl0[1], bl1[0], bl1[1], SWADDR(tBl, row, cb));
                int n0 = 2 * nf2, n1 = 2 * nf2 + 1;
                MMA16816(acc[0][n0], ah[0], bh0);
                MMA16816(acc[0][n1], ah[0], bh1);
                MMA16816(acc[1][n0], ah[1], bh0);
                MMA16816(acc[1][n1], ah[1], bh1);
                MMA16816(acc[0][n0], ah[0], bl0);
                MMA16816(acc[0][n1], ah[0], bl1);
                MMA16816(acc[1][n0], ah[1], bl0);
                MMA16816(acc[1][n1], ah[1], bl1);
                MMA16816(acc[0][n0], al[0], bh0);
                MMA16816(acc[0][n1], al[0], bh1);
                MMA16816(acc[1][n0], al[1], bh0);
                MMA16816(acc[1][n1], al[1], bh1);
            }
        }
        if (c + NSTAGE - 1 < NCHUNK) load_chunk((c + 2) % NSTAGE, (c + 2) * 32);
    }

    if (mode == 0) {
        #pragma unroll
        for (int mf = 0; mf < 2; mf++) {
            int row = ctaM + wm * 32 + mf * 16 + (lane >> 2);
            #pragma unroll
            for (int nf = 0; nf < 8; nf++) {
                int col = ctaN + wn * 64 + nf * 8 + (lane & 3) * 2;
                float bxv = bias[col], byv = bias[col + 1];
                float2 v0 = {acc[mf][nf][0] + bxv, acc[mf][nf][1] + byv};
                float2 v1 = {acc[mf][nf][2] + bxv, acc[mf][nf][3] + byv};
                *(float2*)&C[(size_t)row * Dn + col] = v0;
                *(float2*)&C[(size_t)(row + 8) * Dn + col] = v1;
            }
        }
    } else {
        #pragma unroll
        for (int mf = 0; mf < 2; mf++) {
            int row = ctaM + wm * 32 + mf * 16 + (lane >> 2);
            int b = row >> 10, n = row & 1023;
            #pragma unroll
            for (int nf = 0; nf < 8; nf++) {
                int col = ctaN + wn * 64 + nf * 8 + (lane & 3) * 2;
                int s = col >> 10, hh = (col >> 6) & 15, dh = col & 63;
                float sc = (s == 0) ? 0.125f : 1.0f;
                __nv_bfloat16* hiP = (s == 0) ? qhi : (s == 1) ? khi : vhi;
                __nv_bfloat16* loP = (s == 0) ? qlo : (s == 1) ? klo : vlo;
                size_t o0 = (((size_t)(b * 16 + hh)) * 1024 + n) * 64 + dh;
                size_t o1 = o0 + 8 * 64;
                uint32_t lo;
                uint32_t hi = pack_split(
                    make_float2(acc[mf][nf][0] * sc, acc[mf][nf][1] * sc), lo);
                *(uint32_t*)&hiP[o0] = hi;
                *(uint32_t*)&loP[o0] = lo;
                hi = pack_split(
                    make_float2(acc[mf][nf][2] * sc, acc[mf][nf][3] * sc), lo);
                *(uint32_t*)&hiP[o1] = hi;
                *(uint32_t*)&loP[o1] = lo;
            }
        }
        // arrive: this block's q/k/v slice for batch by>>3 is done
        __syncthreads();
        __threadfence();
        if (tid == 0) atomicAdd(&g_flag_qkv[by >> 3], 1);
    }
}

// ---------------------------------------------------------------------------
// Body: flash attention (R15 version) with qkv spin + row-flag arrive
// ---------------------------------------------------------------------------
#define KSTRIDE 144
#define APLANE (64 * KSTRIDE)
#define OFF_Q   0
#define OFF_STG (2 * APLANE)
#define ASTGB  (4 * APLANE)
#define OFF_MASK (OFF_STG + 2 * ASTGB)
#define OFF_PART (OFF_MASK + 4096)
#define OFF_INV  (OFF_PART + 512)

__device__ __forceinline__ void attn_body(
    int q0, int bh, char* smem,
    const __nv_bfloat16* __restrict__ qhi, const __nv_bfloat16* __restrict__ qlo,
    const __nv_bfloat16* __restrict__ khi, const __nv_bfloat16* __restrict__ klo,
    const __nv_bfloat16* __restrict__ vhi, const __nv_bfloat16* __restrict__ vlo,
    const int* __restrict__ mask, float* __restrict__ attn,
    __nv_bfloat16* __restrict__ hhi, __nv_bfloat16* __restrict__ hlo)
{
    const uint32_t sb = smem_u32(smem);
    const int tid = threadIdx.x, wid = tid >> 5, lane = tid & 31;
    const int q8 = lane >> 3, l8 = lane & 7;
    const int wm = wid & 3, wn = wid >> 2;
    const int b = bh >> 4, h = bh & 15;
    const size_t head_base = (size_t)bh * Nn * DHn;

    // wait for this batch's q/k/v (192 producer blocks)
    if (tid == 0) {
        while (atomicAdd(&g_flag_qkv[b], 0) < 192) __nanosleep(200);
    }
    __syncthreads();

    auto load_tile = [&](int tile, int s) {
        uint32_t stg = sb + OFF_STG + s * ASTGB;
        const __nv_bfloat16* planes[4] = {khi, klo, vhi, vlo};
        #pragma unroll
        for (int i = tid; i < 2048; i += 256) {
            int pl = i >> 9, r = (i >> 3) & 63, c = i & 7;
            const __nv_bfloat16* src = planes[pl] + head_base +
                                       (size_t)(tile * 64 + r) * 64 + c * 8;
            uint32_t dst = stg + pl * APLANE + r * KSTRIDE + c * 16;
            CP_ASYNC16(dst, __cvta_generic_to_global(src));
        }
        CP_COMMIT();
    };

    #pragma unroll
    for (int i = tid; i < 1024; i += 256) {
        int pl = i >> 9, r = (i >> 3) & 63, c = i & 7;
        const __nv_bfloat16* src = (pl ? qlo : qhi) + head_base +
                                   (size_t)(q0 + r) * 64 + c * 8;
        uint32_t dst = sb + OFF_Q + pl * APLANE + r * KSTRIDE + c * 16;
        CP_ASYNC16(dst, __cvta_generic_to_global(src));
    }
    CP_COMMIT();
    load_tile(0, 0);
    load_tile(1, 1);

    {
        int4 mv = ((const int4*)(mask + b * Nn))[tid];
        float4 f = make_float4(mv.x ? 1.f : 0.f, mv.y ? 1.f : 0.f,
                               mv.z ? 1.f : 0.f, mv.w ? 1.f : 0.f);
        ((float4*)(smem + OFF_MASK))[tid] = f;
    }

    uint32_t qfh[4][4], qfl[4][4];
    CP_WAIT2();
    __syncthreads();
    {
        uint32_t qhb = sb + OFF_Q, qlb = sb + OFF_Q + APLANE;
        #pragma unroll
        for (int kk = 0; kk < 4; kk++) {
            uint32_t ao = (uint32_t)((wm * 16 + (q8 & 1) * 8 + l8) * KSTRIDE +
                                     (q8 >> 1) * 16 + kk * 32);
            LDSM_X4(qfh[kk][0], qfh[kk][1], qfh[kk][2], qfh[kk][3], qhb + ao);
            LDSM_X4(qfl[kk][0], qfl[kk][1], qfl[kk][2], qfl[kk][3], qlb + ao);
        }
    }

    const float* mskf = (const float*)(smem + OFF_MASK);
    const int r0 = wm * 16 + (lane >> 2);
    float sum0 = 0.f, sum1 = 0.f;

    float oacc[8][4];
    #pragma unroll
    for (int i = 0; i < 8; i++)
        #pragma unroll
        for (int j = 0; j < 4; j++) oacc[i][j] = 0.f;

    float* attn_row = attn ? attn + ((size_t)bh * Nn + q0 + r0) * Nn : nullptr;

    for (int kt = 0; kt < 16; kt++) {
        if (kt == 15) CP_WAIT0(); else CP_WAIT1();
        __syncthreads();
        uint32_t stg = sb + OFF_STG + (kt & 1) * ASTGB;
        uint32_t khb = stg, klb = stg + APLANE;
        uint32_t vhb = stg + 2 * APLANE, vlb = stg + 3 * APLANE;

        float acc[4][4];
        #pragma unroll
        for (int i = 0; i < 4; i++)
            #pragma unroll
            for (int j = 0; j < 4; j++) acc[i][j] = 0.f;

        #pragma unroll
        for (int kk = 0; kk < 4; kk++) {
            uint32_t bfh[4][2], bfl[4][2];
            #pragma unroll
            for (int pr = 0; pr < 2; pr++) {
                uint32_t bo = (uint32_t)((wn * 32 + pr * 16 + (q8 >> 1) * 8 + l8) * KSTRIDE +
                                         (q8 & 1) * 16 + kk * 32);
                LDSM_X4(bfh[2*pr][0], bfh[2*pr][1], bfh[2*pr+1][0], bfh[2*pr+1][1], khb + bo);
                LDSM_X4(bfl[2*pr][0], bfl[2*pr][1], bfl[2*pr+1][0], bfl[2*pr+1][1], klb + bo);
            }
            #pragma unroll
            for (int nf = 0; nf < 4; nf++) MMA16816(acc[nf], qfh[kk], bfh[nf]);
            #pragma unroll
            for (int nf = 0; nf < 4; nf++) MMA16816(acc[nf], qfh[kk], bfl[nf]);
            #pragma unroll
            for (int nf = 0; nf < 4; nf++) MMA16816(acc[nf], qfl[kk], bfh[nf]);
        }

        #pragma unroll
        for (int nf = 0; nf < 4; nf++) {
            int col = kt * 64 + wn * 32 + nf * 8 + (lane & 3) * 2;
            float2 mv = *(const float2*)&mskf[col];
            acc[nf][0] = __expf(acc[nf][0]) * mv.x;
            acc[nf][1] = __expf(acc[nf][1]) * mv.y;
            acc[nf][2] = __expf(acc[nf][2]) * mv.x;
            acc[nf][3] = __expf(acc[nf][3]) * mv.y;
            sum0 += acc[nf][0] + acc[nf][1];
            sum1 += acc[nf][2] + acc[nf][3];
            if (attn_row) {
                *(float2*)&attn_row[col] = make_float2(acc[nf][0], acc[nf][1]);
                *(float2*)&attn_row[8 * Nn + col] = make_float2(acc[nf][2], acc[nf][3]);
            }
        }

        uint32_t ah[2][4], al[2][4];
        #pragma unroll
        for (int f = 0; f < 2; f++) {
            ah[f][0] = pack_split(make_float2(acc[2*f][0],   acc[2*f][1]),   al[f][0]);
            ah[f][1] = pack_split(make_float2(acc[2*f][2],   acc[2*f][3]),   al[f][1]);
            ah[f][2] = pack_split(make_float2(acc[2*f+1][0], acc[2*f+1][1]), al[f][2]);
            ah[f][3] = pack_split(make_float2(acc[2*f+1][2], acc[2*f+1][3]), al[f][3]);
        }

        #pragma unroll
        for (int f = 0; f < 2; f++) {
            #pragma unroll
            for (int dq = 0; dq < 4; dq++) {
                uint32_t vo = (uint32_t)((wn * 32 + f * 16 + (q8 & 1) * 8 + l8) * KSTRIDE +
                                         dq * 32 + (q8 >> 1) * 16);
                uint32_t vh0[2], vh1[2], vl0[2], vl1[2];
                LDSM_X4_T(vh0[0], vh0[1], vh1[0], vh1[1], vhb + vo);
                LDSM_X4_T(vl0[0], vl0[1], vl1[0], vl1[1], vlb + vo);
                MMA16816(oacc[2*dq],     ah[f], vh0);
                MMA16816(oacc[2*dq + 1], ah[f], vh1);
                MMA16816(oacc[2*dq],     ah[f], vl0);
                MMA16816(oacc[2*dq + 1], ah[f], vl1);
                MMA16816(oacc[2*dq],     al[f], vh0);
                MMA16816(oacc[2*dq + 1], al[f], vh1);
            }
        }

        __syncthreads();
        if (kt + 2 < 16) load_tile(kt + 2, kt & 1);
    }

    sum0 += __shfl_xor_sync(0xffffffffu, sum0, 1);
    sum0 += __shfl_xor_sync(0xffffffffu, sum0, 2);
    sum1 += __shfl_xor_sync(0xffffffffu, sum1, 1);
    sum1 += __shfl_xor_sync(0xffffffffu, sum1, 2);
    {
        float* part = (float*)(smem + OFF_PART);
        if ((lane & 3) == 0) {
            part[wn * 64 + r0]     = sum0;
            part[wn * 64 + r0 + 8] = sum1;
        }
    }
    {
        uint32_t slot = sb + OFF_STG + wid * 4096;
        #pragma unroll
        for (int nt = 0; nt < 8; nt++) {
            uint32_t a0 = slot + (uint32_t)(lane >> 2) * 256 + (nt * 8 + (lane & 3) * 2) * 4;
            *(float2*)(smem + (a0 - sb)) = make_float2(oacc[nt][0], oacc[nt][1]);
            *(float2*)(smem + (a0 - sb) + 8 * 256) = make_float2(oacc[nt][2], oacc[nt][3]);
        }
    }
    __syncthreads();
    {
        const float* part = (const float*)(smem + OFF_PART);
        float* invs = (float*)(smem + OFF_INV);
        if (tid < 64)
            invs[tid] = 1.f / (part[tid] + part[64 + tid]);
    }
    __syncthreads();

    // O reduce, scale, write heads bf16 hi/lo
    {
        const float* invs = (const float*)(smem + OFF_INV);
        int r = wid * 8 + (lane >> 2);
        int c0 = (lane & 3) * 16;
        int strip = r >> 4, rl = r & 15;
        const float* s0 = (const float*)(smem + OFF_STG + strip * 4096) + rl * 64 + c0;
        const float* s1 = (const float*)(smem + OFF_STG + (strip + 4) * 4096) + rl * 64 + c0;
        float inv = invs[r];
        size_t dbase = ((size_t)(b * Nn) + q0 + r) * Dn + h * 64 + c0;
        #pragma unroll
        for (int c = 0; c < 16; c += 2) {
            float v0 = (s0[c]     + s1[c])     * inv;
            float v1 = (s0[c + 1] + s1[c + 1]) * inv;
            uint32_t lo;
            uint32_t hi = pack_split(make_float2(v0, v1), lo);
            *(uint32_t*)&hhi[dbase + c] = hi;
            *(uint32_t*)&hlo[dbase + c] = lo;
        }
    }

    // arrive on row-block flag (h done) BEFORE the attn rescale
    __syncthreads();
    __threadfence();
    if (tid == 0) atomicAdd(&g_flag_row[b * 8 + (q0 >> 7)], 1);

    // in-kernel attn rescale (L2-hot)
    if (attn) {
        const float* invs = (const float*)(smem + OFF_INV);
        float4* attn4 = (float4*)(attn + ((size_t)bh * Nn + q0) * Nn);
        #pragma unroll 4
        for (int i = tid; i < 64 * 256; i += 256) {
            int r = i >> 8;
            float inv = invs[r];
            float4 v = attn4[i];
            v.x *= inv; v.y *= inv; v.z *= inv; v.w *= inv;
            attn4[i] = v;
        }
    }
}

// ---------------------------------------------------------------------------
// Mega-kernel: qkv GEMM (0..1535) | attention (1536..3583) | out GEMM (+512)
// ---------------------------------------------------------------------------
__global__ __launch_bounds__(256, 2) void mega_kernel(
    const __nv_bfloat16* __restrict__ xhi, const __nv_bfloat16* __restrict__ xlo,
    const __nv_bfloat16* __restrict__ wqkvThi, const __nv_bfloat16* __restrict__ wqkvTlo,
    const __nv_bfloat16* __restrict__ woutThi, const __nv_bfloat16* __restrict__ woutTlo,
    __nv_bfloat16* __restrict__ qhi, __nv_bfloat16* __restrict__ qlo,
    __nv_bfloat16* __restrict__ khi, __nv_bfloat16* __restrict__ klo,
    __nv_bfloat16* __restrict__ vhi, __nv_bfloat16* __restrict__ vlo,
    __nv_bfloat16* __restrict__ hhi, __nv_bfloat16* __restrict__ hlo,
    const int* __restrict__ mask, float* __restrict__ attn,
    float* __restrict__ out, const float* __restrict__ b_out)
{
    extern __shared__ char smem[];
    int bid = blockIdx.x;
    if (bid < 1536) {
        // QKV projection, batch-major order (by = bid/24 covers batches 0..7)
        gemm_body(bid % 24, bid / 24, smem, 1,
                  xhi, xlo, wqkvThi, wqkvTlo, nullptr, nullptr,
                  qhi, qlo, khi, klo, vhi, vlo);
    } else if (bid < 3584) {
        int aid = bid - 1536;
        int b = aid >> 8, rem = aid & 255;
        int bh = b * 16 + (rem >> 4);
        int q0 = (rem & 15) * 64;
        attn_body(q0, bh, smem, qhi, qlo, khi, klo, vhi, vlo,
                  mask, attn, hhi, hlo);
    } else {
        int oid = bid - 3584;
        int obx = oid & 7, oby = oid >> 3;
        // wait for this 128-token row block of h (32 attn producers)
        if (threadIdx.x == 0) {
            while (atomicAdd(&g_flag_row[oby], 0) < 32) __nanosleep(200);
        }
        __syncthreads();
        gemm_body(obx, oby, smem, 0,
                  hhi, hlo, woutThi, woutTlo, out, b_out,
                  nullptr, nullptr, nullptr, nullptr, nullptr, nullptr);
    }
}

// ---------------------------------------------------------------------------

extern "C" void kernel_launch(void* const* d_in, const int* in_sizes, int n_in,
                              void* d_out, int out_size)
{
    const float* x     = (const float*)d_in[0];
    const int*   mask  = (const int*)d_in[1];
    const float* w_qkv = (const float*)d_in[2];
    const float* w_out = (const float*)d_in[3];
    const float* b_out = (const float*)d_in[4];

    float* out = (float*)d_out;
    const size_t out_elems  = (size_t)Bn * Nn * Dn;
    const size_t attn_elems = (size_t)Bn * Hn * Nn * Nn;
    float* attn = ((size_t)out_size >= out_elems + attn_elems) ? out + out_elems : nullptr;

    __nv_bfloat16 *xhi, *xlo, *wqkvThi, *wqkvTlo, *woutThi, *woutTlo, *hhi, *hlo;
    __nv_bfloat16 *qhi, *qlo, *khi, *klo, *vhi, *vlo;
    cudaGetSymbolAddress((void**)&xhi, g_xhi);
    cudaGetSymbolAddress((void**)&xlo, g_xlo);
    cudaGetSymbolAddress((void**)&wqkvThi, g_wqkvThi);
    cudaGetSymbolAddress((void**)&wqkvTlo, g_wqkvTlo);
    cudaGetSymbolAddress((void**)&woutThi, g_woutThi);
    cudaGetSymbolAddress((void**)&woutTlo, g_woutTlo);
    cudaGetSymbolAddress((void**)&hhi, g_hhi);
    cudaGetSymbolAddress((void**)&hlo, g_hlo);
    cudaGetSymbolAddress((void**)&qhi, g_qhi);
    cudaGetSymbolAddress((void**)&qlo, g_qlo);
    cudaGetSymbolAddress((void**)&khi, g_khi);
    cudaGetSymbolAddress((void**)&klo, g_klo);
    cudaGetSymbolAddress((void**)&vhi, g_vhi);
    cudaGetSymbolAddress((void**)&vlo, g_vlo);

    cudaFuncSetAttribute(mega_kernel, cudaFuncAttributeMaxDynamicSharedMemorySize,
                         SMEM_MEGA);

    const int n4x = (Bn * Nn * Dn) / 4;

    // 1) splits (split_kernel also zeroes the dataflow flags)
    split_kernel<<<(n4x + 255) / 256, 256>>>((const float4*)x,
                                             (__nv_bfloat162*)xhi, (__nv_bfloat162*)xlo, n4x);
    splitT_kernel<<<dim3(D3 / 32, Dn / 32), dim3(32, 8)>>>(w_qkv, wqkvThi, wqkvTlo, Dn, D3);
    splitT_kernel<<<dim3(Dn / 32, Dn / 32), dim3(32, 8)>>>(w_out, woutThi, woutTlo, Dn, Dn);

    // 2) mega-kernel: qkv GEMM -> attention -> out GEMM with flag dataflow
    mega_kernel<<<4096, 256, SMEM_MEGA>>>(
        xhi, xlo, wqkvThi, wqkvTlo, woutThi, woutTlo,
        qhi, qlo, khi, klo, vhi, vlo, hhi, hlo,
        mask, attn, out, b_out);
}

// round 17
// speedup vs baseline: 1.2411x; 1.0152x over previous
#include <cuda_runtime.h>
#include <cuda_bf16.h>
#include <cstdint>

// Problem constants
#define Bn 8
#define Nn 1024
#define Dn 1024
#define Hn 16
#define DHn 64
#define D3 3072
#define Kdim 1024

// ---------------------------------------------------------------------------
// Device scratch (allocation-free)
// ---------------------------------------------------------------------------
__device__ __nv_bfloat16 g_xhi[(size_t)Bn * Nn * Dn];
__device__ __nv_bfloat16 g_xlo[(size_t)Bn * Nn * Dn];
__device__ __nv_bfloat16 g_wqkvThi[(size_t)D3 * Dn];
__device__ __nv_bfloat16 g_wqkvTlo[(size_t)D3 * Dn];
__device__ __nv_bfloat16 g_woutThi[(size_t)Dn * Dn];
__device__ __nv_bfloat16 g_woutTlo[(size_t)Dn * Dn];
__device__ __nv_bfloat16 g_hhi[(size_t)Bn * Nn * Dn];
__device__ __nv_bfloat16 g_hlo[(size_t)Bn * Nn * Dn];
#define HEADELEMS ((size_t)Bn * Hn * Nn * DHn)
__device__ __nv_bfloat16 g_qhi[HEADELEMS];
__device__ __nv_bfloat16 g_qlo[HEADELEMS];
__device__ __nv_bfloat16 g_khi[HEADELEMS];
__device__ __nv_bfloat16 g_klo[HEADELEMS];
__device__ __nv_bfloat16 g_vhi[HEADELEMS];
__device__ __nv_bfloat16 g_vlo[HEADELEMS];
// dataflow flags (zeroed by split_kernel each launch)
__device__ int g_flag_qkv[8];     // per batch: 192 gemm_qkv producers
__device__ int g_flag_row[64];    // per 128-token block: 32 attn producers

// ---------------------------------------------------------------------------
// PTX helpers (baseline sm_80+ features only)
// ---------------------------------------------------------------------------
__device__ __forceinline__ uint32_t smem_u32(const void* p) {
    uint32_t a;
    asm("{ .reg .u64 t; cvta.to.shared.u64 t, %1; cvt.u32.u64 %0, t; }"
        : "=r"(a) : "l"(p));
    return a;
}

#define CP_ASYNC16(dst, gsrc) \
    asm volatile("cp.async.cg.shared.global [%0], [%1], 16;" :: "r"(dst), "l"(gsrc))
#define CP_COMMIT() asm volatile("cp.async.commit_group;" ::: "memory")
#define CP_WAIT2()  asm volatile("cp.async.wait_group 2;" ::: "memory")
#define CP_WAIT1()  asm volatile("cp.async.wait_group 1;" ::: "memory")
#define CP_WAIT0()  asm volatile("cp.async.wait_group 0;" ::: "memory")

#define LDSM_X4(r0, r1, r2, r3, addr) \
    asm volatile("ldmatrix.sync.aligned.m8n8.x4.shared.b16 {%0,%1,%2,%3}, [%4];" \
                 : "=r"(r0), "=r"(r1), "=r"(r2), "=r"(r3) : "r"(addr))

#define LDSM_X4_T(r0, r1, r2, r3, addr) \
    asm volatile("ldmatrix.sync.aligned.m8n8.x4.trans.shared.b16 {%0,%1,%2,%3}, [%4];" \
                 : "=r"(r0), "=r"(r1), "=r"(r2), "=r"(r3) : "r"(addr))

#define MMA16816(d, a, b) \
    asm volatile("mma.sync.aligned.m16n8k16.row.col.f32.bf16.bf16.f32 " \
                 "{%0,%1,%2,%3}, {%4,%5,%6,%7}, {%8,%9}, {%0,%1,%2,%3};" \
                 : "+f"((d)[0]), "+f"((d)[1]), "+f"((d)[2]), "+f"((d)[3]) \
                 : "r"((a)[0]), "r"((a)[1]), "r"((a)[2]), "r"((a)[3]), \
                   "r"((b)[0]), "r"((b)[1]))

__device__ __forceinline__ uint32_t pack_split(float2 p, uint32_t& lo) {
    __nv_bfloat16 hx = __float2bfloat16(p.x), hy = __float2bfloat16(p.y);
    __nv_bfloat16 lx = __float2bfloat16(p.x - __bfloat162float(hx));
    __nv_bfloat16 ly = __float2bfloat16(p.y - __bfloat162float(hy));
    __nv_bfloat162 hv = __halves2bfloat162(hx, hy);
    __nv_bfloat162 lv = __halves2bfloat162(lx, ly);
    lo = *(uint32_t*)&lv;
    return *(uint32_t*)&hv;
}

// swizzled address in a 64B-row tile (gemm): chunk c ^ ((row>>1)&3)
#define SWADDR(base, row, c) \
    ((base) + (uint32_t)(row) * 64u + ((uint32_t)((c) ^ (((row) >> 1) & 3)) << 4))

// ---------------------------------------------------------------------------
// Split kernels (split_kernel also zeroes the dataflow flags)
// ---------------------------------------------------------------------------
__global__ __launch_bounds__(256) void split_kernel(
    const float4* __restrict__ in, __nv_bfloat162* __restrict__ hi,
    __nv_bfloat162* __restrict__ lo, int n4)
{
    if (blockIdx.x == 0 && threadIdx.x < 72) {
        if (threadIdx.x < 8) g_flag_qkv[threadIdx.x] = 0;
        else g_flag_row[threadIdx.x - 8] = 0;
    }
    int i = blockIdx.x * 256 + threadIdx.x;
    if (i >= n4) return;
    float4 v = in[i];
    __nv_bfloat16 h0 = __float2bfloat16(v.x), h1 = __float2bfloat16(v.y);
    __nv_bfloat16 h2 = __float2bfloat16(v.z), h3 = __float2bfloat16(v.w);
    __nv_bfloat16 l0 = __float2bfloat16(v.x - __bfloat162float(h0));
    __nv_bfloat16 l1 = __float2bfloat16(v.y - __bfloat162float(h1));
    __nv_bfloat16 l2 = __float2bfloat16(v.z - __bfloat162float(h2));
    __nv_bfloat16 l3 = __float2bfloat16(v.w - __bfloat162float(h3));
    hi[2 * i]     = __halves2bfloat162(h0, h1);
    hi[2 * i + 1] = __halves2bfloat162(h2, h3);
    lo[2 * i]     = __halves2bfloat162(l0, l1);
    lo[2 * i + 1] = __halves2bfloat162(l2, l3);
}

__global__ __launch_bounds__(256) void splitT_kernel(
    const float* __restrict__ in, __nv_bfloat16* __restrict__ hiT,
    __nv_bfloat16* __restrict__ loT, int R, int C)
{
    __shared__ float t[32][33];
    int bx = blockIdx.x * 32;
    int by = blockIdx.y * 32;
    int x = threadIdx.x, y = threadIdx.y;  // 32 x 8
    #pragma unroll
    for (int i = y; i < 32; i += 8)
        t[i][x] = in[(size_t)(by + i) * C + bx + x];
    __syncthreads();
    #pragma unroll
    for (int i = y; i < 32; i += 8) {
        float v = t[x][i];
        __nv_bfloat16 h = __float2bfloat16(v);
        size_t o = (size_t)(bx + i) * R + by + x;
        hiT[o] = h;
        loT[o] = __float2bfloat16(v - __bfloat162float(h));
    }
}

// ---------------------------------------------------------------------------
// Shared tile sizes
// ---------------------------------------------------------------------------
#define TILEB (128 * 64)
#define STAGEB (4 * TILEB)
#define NSTAGE 3
#define SMEM_MEGA (NSTAGE * STAGEB)    // 98304
#define NCHUNK (Kdim / 32)

// ---------------------------------------------------------------------------
// Body: bf16-split GEMM (shared by qkv/out modes)
// mode 1: per-head split write + flag_qkv arrive.  mode 0: C+bias.
// ---------------------------------------------------------------------------
__device__ __forceinline__ void gemm_body(
    int bx, int by, char* smem, int mode,
    const __nv_bfloat16* __restrict__ Ahi, const __nv_bfloat16* __restrict__ Alo,
    const __nv_bfloat16* __restrict__ BThi, const __nv_bfloat16* __restrict__ BTlo,
    float* __restrict__ C, const float* __restrict__ bias,
    __nv_bfloat16* __restrict__ qhi, __nv_bfloat16* __restrict__ qlo,
    __nv_bfloat16* __restrict__ khi, __nv_bfloat16* __restrict__ klo,
    __nv_bfloat16* __restrict__ vhi, __nv_bfloat16* __restrict__ vlo)
{
    const uint32_t sb = smem_u32(smem);
    const int tid = threadIdx.x, wid = tid >> 5, lane = tid & 31;
    const int wm = wid >> 1;
    const int wn = wid & 1;
    const int ctaM = by * 128, ctaN = bx * 128;

    const __nv_bfloat16* gsrc[4] = {
        Ahi + (size_t)ctaM * Kdim, Alo + (size_t)ctaM * Kdim,
        BThi + (size_t)ctaN * Kdim, BTlo + (size_t)ctaN * Kdim};

    auto load_chunk = [&](int s, int k0) {
        uint32_t base = sb + s * STAGEB;
        #pragma unroll
        for (int t = 0; t < 4; t++) {
            uint32_t tb = base + t * TILEB;
            const __nv_bfloat16* g = gsrc[t] + k0;
            #pragma unroll
            for (int i = tid; i < 512; i += 256) {
                int r = i >> 2, c = i & 3;
                uint32_t dst = SWADDR(tb, r, c);
                size_t gs = __cvta_generic_to_global(g + (size_t)r * Kdim + c * 8);
                CP_ASYNC16(dst, gs);
            }
        }
        CP_COMMIT();
    };

    float acc[2][8][4];
    #pragma unroll
    for (int i = 0; i < 2; i++)
        #pragma unroll
        for (int j = 0; j < 8; j++)
            #pragma unroll
            for (int k = 0; k < 4; k++) acc[i][j][k] = 0.f;

    load_chunk(0, 0);
    load_chunk(1, 32);

    const int q = lane >> 3, l8 = lane & 7;
    const int arow = wm * 32 + (q & 1) * 8 + l8;
    const int brow = wn * 64 + (q >> 1) * 8 + l8;
    const int acsel = q >> 1;
    const int bcsel = q & 1;

    for (int c = 0; c < NCHUNK; c++) {
        int s = c % NSTAGE;
        if (c == NCHUNK - 1) CP_WAIT0(); else CP_WAIT1();
        __syncthreads();

        uint32_t base = sb + s * STAGEB;
        uint32_t tAh = base, tAl = base + TILEB;
        uint32_t tBh = base + 2 * TILEB, tBl = base + 3 * TILEB;

        #pragma unroll
        for (int kk = 0; kk < 2; kk++) {
            int ca = kk * 2 + acsel;
            int cb = kk * 2 + bcsel;
            uint32_t ah[2][4], al[2][4];
            #pragma unroll
            for (int mf = 0; mf < 2; mf++) {
                int row = arow + mf * 16;
                LDSM_X4(ah[mf][0], ah[mf][1], ah[mf][2], ah[mf][3], SWADDR(tAh, row, ca));
                LDSM_X4(al[mf][0], al[mf][1], al[mf][2], al[mf][3], SWADDR(tAl, row, ca));
            }
            #pragma unroll
            for (int nf2 = 0; nf2 < 4; nf2++) {
                uint32_t bh0[2], bh1[2], bl0[2], bl1[2];
                int row = brow + nf2 * 16;
                LDSM_X4(bh0[0], bh0[1], bh1[0], bh1[1], SWADDR(tBh, row, cb));
                LDSM_X4(bl0[0], bl0[1], bl1[0], bl1[1], SWADDR(tBl, row, cb));
                int n0 = 2 * nf2, n1 = 2 * nf2 + 1;
                MMA16816(acc[0][n0], ah[0], bh0);
                MMA16816(acc[0][n1], ah[0], bh1);
                MMA16816(acc[1][n0], ah[1], bh0);
                MMA16816(acc[1][n1], ah[1], bh1);
                MMA16816(acc[0][n0], ah[0], bl0);
                MMA16816(acc[0][n1], ah[0], bl1);
                MMA16816(acc[1][n0], ah[1], bl0);
                MMA16816(acc[1][n1], ah[1], bl1);
                MMA16816(acc[0][n0], al[0], bh0);
                MMA16816(acc[0][n1], al[0], bh1);
                MMA16816(acc[1][n0], al[1], bh0);
                MMA16816(acc[1][n1], al[1], bh1);
            }
        }
        if (c + NSTAGE - 1 < NCHUNK) load_chunk((c + 2) % NSTAGE, (c + 2) * 32);
    }

    if (mode == 0) {
        #pragma unroll
        for (int mf = 0; mf < 2; mf++) {
            int row = ctaM + wm * 32 + mf * 16 + (lane >> 2);
            #pragma unroll
            for (int nf = 0; nf < 8; nf++) {
                int col = ctaN + wn * 64 + nf * 8 + (lane & 3) * 2;
                float bxv = bias[col], byv = bias[col + 1];
                float2 v0 = {acc[mf][nf][0] + bxv, acc[mf][nf][1] + byv};
                float2 v1 = {acc[mf][nf][2] + bxv, acc[mf][nf][3] + byv};
                *(float2*)&C[(size_t)row * Dn + col] = v0;
                *(float2*)&C[(size_t)(row + 8) * Dn + col] = v1;
            }
        }
    } else {
        #pragma unroll
        for (int mf = 0; mf < 2; mf++) {
            int row = ctaM + wm * 32 + mf * 16 + (lane >> 2);
            int b = row >> 10, n = row & 1023;
            #pragma unroll
            for (int nf = 0; nf < 8; nf++) {
                int col = ctaN + wn * 64 + nf * 8 + (lane & 3) * 2;
                int s = col >> 10, hh = (col >> 6) & 15, dh = col & 63;
                float sc = (s == 0) ? 0.125f : 1.0f;
                __nv_bfloat16* hiP = (s == 0) ? qhi : (s == 1) ? khi : vhi;
                __nv_bfloat16* loP = (s == 0) ? qlo : (s == 1) ? klo : vlo;
                size_t o0 = (((size_t)(b * 16 + hh)) * 1024 + n) * 64 + dh;
                size_t o1 = o0 + 8 * 64;
                uint32_t lo;
                uint32_t hi = pack_split(
                    make_float2(acc[mf][nf][0] * sc, acc[mf][nf][1] * sc), lo);
                *(uint32_t*)&hiP[o0] = hi;
                *(uint32_t*)&loP[o0] = lo;
                hi = pack_split(
                    make_float2(acc[mf][nf][2] * sc, acc[mf][nf][3] * sc), lo);
                *(uint32_t*)&hiP[o1] = hi;
                *(uint32_t*)&loP[o1] = lo;
            }
        }
        // arrive: this block's q/k/v slice for batch by>>3 is done
        __syncthreads();
        __threadfence();
        if (tid == 0) atomicAdd(&g_flag_qkv[by >> 3], 1);
    }
}

// ---------------------------------------------------------------------------
// Body: flash attention with qkv spin + row-flag arrive
// ---------------------------------------------------------------------------
#define KSTRIDE 144
#define APLANE (64 * KSTRIDE)
#define OFF_Q   0
#define OFF_STG (2 * APLANE)
#define ASTGB  (4 * APLANE)
#define OFF_MASK (OFF_STG + 2 * ASTGB)
#define OFF_PART (OFF_MASK + 4096)
#define OFF_INV  (OFF_PART + 512)

__device__ __forceinline__ void attn_body(
    int q0, int bh, char* smem,
    const __nv_bfloat16* __restrict__ qhi, const __nv_bfloat16* __restrict__ qlo,
    const __nv_bfloat16* __restrict__ khi, const __nv_bfloat16* __restrict__ klo,
    const __nv_bfloat16* __restrict__ vhi, const __nv_bfloat16* __restrict__ vlo,
    const int* __restrict__ mask, float* __restrict__ attn,
    __nv_bfloat16* __restrict__ hhi, __nv_bfloat16* __restrict__ hlo)
{
    const uint32_t sb = smem_u32(smem);
    const int tid = threadIdx.x, wid = tid >> 5, lane = tid & 31;
    const int q8 = lane >> 3, l8 = lane & 7;
    const int wm = wid & 3, wn = wid >> 2;
    const int b = bh >> 4, h = bh & 15;
    const size_t head_base = (size_t)bh * Nn * DHn;

    // wait for this batch's q/k/v (192 producer blocks)
    if (tid == 0) {
        while (atomicAdd(&g_flag_qkv[b], 0) < 192) __nanosleep(200);
    }
    __syncthreads();

    auto load_tile = [&](int tile, int s) {
        uint32_t stg = sb + OFF_STG + s * ASTGB;
        const __nv_bfloat16* planes[4] = {khi, klo, vhi, vlo};
        #pragma unroll
        for (int i = tid; i < 2048; i += 256) {
            int pl = i >> 9, r = (i >> 3) & 63, c = i & 7;
            const __nv_bfloat16* src = planes[pl] + head_base +
                                       (size_t)(tile * 64 + r) * 64 + c * 8;
            uint32_t dst = stg + pl * APLANE + r * KSTRIDE + c * 16;
            CP_ASYNC16(dst, __cvta_generic_to_global(src));
        }
        CP_COMMIT();
    };

    #pragma unroll
    for (int i = tid; i < 1024; i += 256) {
        int pl = i >> 9, r = (i >> 3) & 63, c = i & 7;
        const __nv_bfloat16* src = (pl ? qlo : qhi) + head_base +
                                   (size_t)(q0 + r) * 64 + c * 8;
        uint32_t dst = sb + OFF_Q + pl * APLANE + r * KSTRIDE + c * 16;
        CP_ASYNC16(dst, __cvta_generic_to_global(src));
    }
    CP_COMMIT();
    load_tile(0, 0);
    load_tile(1, 1);

    {
        int4 mv = ((const int4*)(mask + b * Nn))[tid];
        float4 f = make_float4(mv.x ? 1.f : 0.f, mv.y ? 1.f : 0.f,
                               mv.z ? 1.f : 0.f, mv.w ? 1.f : 0.f);
        ((float4*)(smem + OFF_MASK))[tid] = f;
    }

    uint32_t qfh[4][4], qfl[4][4];
    CP_WAIT2();
    __syncthreads();
    {
        uint32_t qhb = sb + OFF_Q, qlb = sb + OFF_Q + APLANE;
        #pragma unroll
        for (int kk = 0; kk < 4; kk++) {
            uint32_t ao = (uint32_t)((wm * 16 + (q8 & 1) * 8 + l8) * KSTRIDE +
                                     (q8 >> 1) * 16 + kk * 32);
            LDSM_X4(qfh[kk][0], qfh[kk][1], qfh[kk][2], qfh[kk][3], qhb + ao);
            LDSM_X4(qfl[kk][0], qfl[kk][1], qfl[kk][2], qfl[kk][3], qlb + ao);
        }
    }

    const float* mskf = (const float*)(smem + OFF_MASK);
    const int r0 = wm * 16 + (lane >> 2);
    float sum0 = 0.f, sum1 = 0.f;

    float oacc[8][4];
    #pragma unroll
    for (int i = 0; i < 8; i++)
        #pragma unroll
        for (int j = 0; j < 4; j++) oacc[i][j] = 0.f;

    float* attn_row = attn ? attn + ((size_t)bh * Nn + q0 + r0) * Nn : nullptr;

    for (int kt = 0; kt < 16; kt++) {
        if (kt == 15) CP_WAIT0(); else CP_WAIT1();
        __syncthreads();
        uint32_t stg = sb + OFF_STG + (kt & 1) * ASTGB;
        uint32_t khb = stg, klb = stg + APLANE;
        uint32_t vhb = stg + 2 * APLANE, vlb = stg + 3 * APLANE;

        float acc[4][4];
        #pragma unroll
        for (int i = 0; i < 4; i++)
            #pragma unroll
            for (int j = 0; j < 4; j++) acc[i][j] = 0.f;

        #pragma unroll
        for (int kk = 0; kk < 4; kk++) {
            uint32_t bfh[4][2], bfl[4][2];
            #pragma unroll
            for (int pr = 0; pr < 2; pr++) {
                uint32_t bo = (uint32_t)((wn * 32 + pr * 16 + (q8 >> 1) * 8 + l8) * KSTRIDE +
                                         (q8 & 1) * 16 + kk * 32);
                LDSM_X4(bfh[2*pr][0], bfh[2*pr][1], bfh[2*pr+1][0], bfh[2*pr+1][1], khb + bo);
                LDSM_X4(bfl[2*pr][0], bfl[2*pr][1], bfl[2*pr+1][0], bfl[2*pr+1][1], klb + bo);
            }
            #pragma unroll
            for (int nf = 0; nf < 4; nf++) MMA16816(acc[nf], qfh[kk], bfh[nf]);
            #pragma unroll
            for (int nf = 0; nf < 4; nf++) MMA16816(acc[nf], qfh[kk], bfl[nf]);
            #pragma unroll
            for (int nf = 0; nf < 4; nf++) MMA16816(acc[nf], qfl[kk], bfh[nf]);
        }

        #pragma unroll
        for (int nf = 0; nf < 4; nf++) {
            int col = kt * 64 + wn * 32 + nf * 8 + (lane & 3) * 2;
            float2 mv = *(const float2*)&mskf[col];
            acc[nf][0] = __expf(acc[nf][0]) * mv.x;
            acc[nf][1] = __expf(acc[nf][1]) * mv.y;
            acc[nf][2] = __expf(acc[nf][2]) * mv.x;
            acc[nf][3] = __expf(acc[nf][3]) * mv.y;
            sum0 += acc[nf][0] + acc[nf][1];
            sum1 += acc[nf][2] + acc[nf][3];
            if (attn_row) {
                *(float2*)&attn_row[col] = make_float2(acc[nf][0], acc[nf][1]);
                *(float2*)&attn_row[8 * Nn + col] = make_float2(acc[nf][2], acc[nf][3]);
            }
        }

        uint32_t ah[2][4], al[2][4];
        #pragma unroll
        for (int f = 0; f < 2; f++) {
            ah[f][0] = pack_split(make_float2(acc[2*f][0],   acc[2*f][1]),   al[f][0]);
            ah[f][1] = pack_split(make_float2(acc[2*f][2],   acc[2*f][3]),   al[f][1]);
            ah[f][2] = pack_split(make_float2(acc[2*f+1][0], acc[2*f+1][1]), al[f][2]);
            ah[f][3] = pack_split(make_float2(acc[2*f+1][2], acc[2*f+1][3]), al[f][3]);
        }

        #pragma unroll
        for (int f = 0; f < 2; f++) {
            #pragma unroll
            for (int dq = 0; dq < 4; dq++) {
                uint32_t vo = (uint32_t)((wn * 32 + f * 16 + (q8 & 1) * 8 + l8) * KSTRIDE +
                                         dq * 32 + (q8 >> 1) * 16);
                uint32_t vh0[2], vh1[2], vl0[2], vl1[2];
                LDSM_X4_T(vh0[0], vh0[1], vh1[0], vh1[1], vhb + vo);
                LDSM_X4_T(vl0[0], vl0[1], vl1[0], vl1[1], vlb + vo);
                MMA16816(oacc[2*dq],     ah[f], vh0);
                MMA16816(oacc[2*dq + 1], ah[f], vh1);
                MMA16816(oacc[2*dq],     ah[f], vl0);
                MMA16816(oacc[2*dq + 1], ah[f], vl1);
                MMA16816(oacc[2*dq],     al[f], vh0);
                MMA16816(oacc[2*dq + 1], al[f], vh1);
            }
        }

        __syncthreads();
        if (kt + 2 < 16) load_tile(kt + 2, kt & 1);
    }

    sum0 += __shfl_xor_sync(0xffffffffu, sum0, 1);
    sum0 += __shfl_xor_sync(0xffffffffu, sum0, 2);
    sum1 += __shfl_xor_sync(0xffffffffu, sum1, 1);
    sum1 += __shfl_xor_sync(0xffffffffu, sum1, 2);
    {
        float* part = (float*)(smem + OFF_PART);
        if ((lane & 3) == 0) {
            part[wn * 64 + r0]     = sum0;
            part[wn * 64 + r0 + 8] = sum1;
        }
    }
    {
        uint32_t slot = sb + OFF_STG + wid * 4096;
        #pragma unroll
        for (int nt = 0; nt < 8; nt++) {
            uint32_t a0 = slot + (uint32_t)(lane >> 2) * 256 + (nt * 8 + (lane & 3) * 2) * 4;
            *(float2*)(smem + (a0 - sb)) = make_float2(oacc[nt][0], oacc[nt][1]);
            *(float2*)(smem + (a0 - sb) + 8 * 256) = make_float2(oacc[nt][2], oacc[nt][3]);
        }
    }
    __syncthreads();
    {
        const float* part = (const float*)(smem + OFF_PART);
        float* invs = (float*)(smem + OFF_INV);
        if (tid < 64)
            invs[tid] = 1.f / (part[tid] + part[64 + tid]);
    }
    __syncthreads();

    // O reduce, scale, write heads bf16 hi/lo
    {
        const float* invs = (const float*)(smem + OFF_INV);
        int r = wid * 8 + (lane >> 2);
        int c0 = (lane & 3) * 16;
        int strip = r >> 4, rl = r & 15;
        const float* s0 = (const float*)(smem + OFF_STG + strip * 4096) + rl * 64 + c0;
        const float* s1 = (const float*)(smem + OFF_STG + (strip + 4) * 4096) + rl * 64 + c0;
        float inv = invs[r];
        size_t dbase = ((size_t)(b * Nn) + q0 + r) * Dn + h * 64 + c0;
        #pragma unroll
        for (int c = 0; c < 16; c += 2) {
            float v0 = (s0[c]     + s1[c])     * inv;
            float v1 = (s0[c + 1] + s1[c + 1]) * inv;
            uint32_t lo;
            uint32_t hi = pack_split(make_float2(v0, v1), lo);
            *(uint32_t*)&hhi[dbase + c] = hi;
            *(uint32_t*)&hlo[dbase + c] = lo;
        }
    }

    // arrive on row-block flag (h done) BEFORE the attn rescale
    __syncthreads();
    __threadfence();
    if (tid == 0) atomicAdd(&g_flag_row[b * 8 + (q0 >> 7)], 1);

    // in-kernel attn rescale (L2-hot)
    if (attn) {
        const float* invs = (const float*)(smem + OFF_INV);
        float4* attn4 = (float4*)(attn + ((size_t)bh * Nn + q0) * Nn);
        #pragma unroll 4
        for (int i = tid; i < 64 * 256; i += 256) {
            int r = i >> 8;
            float inv = invs[r];
            float4 v = attn4[i];
            v.x *= inv; v.y *= inv; v.z *= inv; v.w *= inv;
            attn4[i] = v;
        }
    }
}

// ---------------------------------------------------------------------------
// Mega-kernel: qkv GEMM (0..1535) | attention (1536..3583, q-major) |
// out GEMM (3584..4095).
// ---------------------------------------------------------------------------
__global__ __launch_bounds__(256, 2) void mega_kernel(
    const __nv_bfloat16* __restrict__ xhi, const __nv_bfloat16* __restrict__ xlo,
    const __nv_bfloat16* __restrict__ wqkvThi, const __nv_bfloat16* __restrict__ wqkvTlo,
    const __nv_bfloat16* __restrict__ woutThi, const __nv_bfloat16* __restrict__ woutTlo,
    __nv_bfloat16* __restrict__ qhi, __nv_bfloat16* __restrict__ qlo,
    __nv_bfloat16* __restrict__ khi, __nv_bfloat16* __restrict__ klo,
    __nv_bfloat16* __restrict__ vhi, __nv_bfloat16* __restrict__ vlo,
    __nv_bfloat16* __restrict__ hhi, __nv_bfloat16* __restrict__ hlo,
    const int* __restrict__ mask, float* __restrict__ attn,
    float* __restrict__ out, const float* __restrict__ b_out)
{
    extern __shared__ char smem[];
    int bid = blockIdx.x;
    if (bid < 1536) {
        // QKV projection, batch-major order (by = bid/24 covers batches 0..7)
        gemm_body(bid % 24, bid / 24, smem, 1,
                  xhi, xlo, wqkvThi, wqkvTlo, nullptr, nullptr,
                  qhi, qlo, khi, klo, vhi, vlo);
    } else if (bid < 3584) {
        // attention, q-major within batch: (b, q0, h) so each 128-token row
        // block's 32 producers are contiguous -> rows complete in dispatch
        // order -> out blocks overlap the attn drain.
        int aid = bid - 1536;
        int b = aid >> 8, rem = aid & 255;
        int q0 = (rem >> 4) * 64;
        int bh = b * 16 + (rem & 15);
        attn_body(q0, bh, smem, qhi, qlo, khi, klo, vhi, vlo,
                  mask, attn, hhi, hlo);
    } else {
        int oid = bid - 3584;
        int obx = oid & 7, oby = oid >> 3;
        // wait for this 128-token row block of h (32 attn producers)
        if (threadIdx.x == 0) {
            while (atomicAdd(&g_flag_row[oby], 0) < 32) __nanosleep(200);
        }
        __syncthreads();
        gemm_body(obx, oby, smem, 0,
                  hhi, hlo, woutThi, woutTlo, out, b_out,
                  nullptr, nullptr, nullptr, nullptr, nullptr, nullptr);
    }
}

// ---------------------------------------------------------------------------

extern "C" void kernel_launch(void* const* d_in, const int* in_sizes, int n_in,
                              void* d_out, int out_size)
{
    const float* x     = (const float*)d_in[0];
    const int*   mask  = (const int*)d_in[1];
    const float* w_qkv = (const float*)d_in[2];
    const float* w_out = (const float*)d_in[3];
    const float* b_out = (const float*)d_in[4];

    float* out = (float*)d_out;
    const size_t out_elems  = (size_t)Bn * Nn * Dn;
    const size_t attn_elems = (size_t)Bn * Hn * Nn * Nn;
    float* attn = ((size_t)out_size >= out_elems + attn_elems) ? out + out_elems : nullptr;

    __nv_bfloat16 *xhi, *xlo, *wqkvThi, *wqkvTlo, *woutThi, *woutTlo, *hhi, *hlo;
    __nv_bfloat16 *qhi, *qlo, *khi, *klo, *vhi, *vlo;
    cudaGetSymbolAddress((void**)&xhi, g_xhi);
    cudaGetSymbolAddress((void**)&xlo, g_xlo);
    cudaGetSymbolAddress((void**)&wqkvThi, g_wqkvThi);
    cudaGetSymbolAddress((void**)&wqkvTlo, g_wqkvTlo);
    cudaGetSymbolAddress((void**)&woutThi, g_woutThi);
    cudaGetSymbolAddress((void**)&woutTlo, g_woutTlo);
    cudaGetSymbolAddress((void**)&hhi, g_hhi);
    cudaGetSymbolAddress((void**)&hlo, g_hlo);
    cudaGetSymbolAddress((void**)&qhi, g_qhi);
    cudaGetSymbolAddress((void**)&qlo, g_qlo);
    cudaGetSymbolAddress((void**)&khi, g_khi);
    cudaGetSymbolAddress((void**)&klo, g_klo);
    cudaGetSymbolAddress((void**)&vhi, g_vhi);
    cudaGetSymbolAddress((void**)&vlo, g_vlo);

    cudaFuncSetAttribute(mega_kernel, cudaFuncAttributeMaxDynamicSharedMemorySize,
                         SMEM_MEGA);

    const int n4x = (Bn * Nn * Dn) / 4;

    // 1) splits (split_kernel also zeroes the dataflow flags)
    split_kernel<<<(n4x + 255) / 256, 256>>>((const float4*)x,
                                             (__nv_bfloat162*)xhi, (__nv_bfloat162*)xlo, n4x);
    splitT_kernel<<<dim3(D3 / 32, Dn / 32), dim3(32, 8)>>>(w_qkv, wqkvThi, wqkvTlo, Dn, D3);
    splitT_kernel<<<dim3(Dn / 32, Dn / 32), dim3(32, 8)>>>(w_out, woutThi, woutTlo, Dn, Dn);

    // 2) mega-kernel: qkv GEMM -> attention (q-major) -> out GEMM
    mega_kernel<<<4096, 256, SMEM_MEGA>>>(
        xhi, xlo, wqkvThi, wqkvTlo, woutThi, woutTlo,
        qhi, qlo, khi, klo, vhi, vlo, hhi, hlo,
        mask, attn, out, b_out);
}